// round 11
// baseline (speedup 1.0000x reference)
#include <cuda_runtime.h>
#include <cuda_fp16.h>
#include <math.h>
#include <stdint.h>
#include <stddef.h>

#define B_   2
#define S_   2048
#define HID_ 2048
#define H_   16
#define HS_  128
#define RD_  32

// ---------------- scratch (device globals) ----------------
__device__ float g_qkv[(size_t)B_ * S_ * 3 * HID_];

__device__ __half g_Ahi[(size_t)B_ * S_ * HID_];
__device__ __half g_Alo[(size_t)B_ * S_ * HID_];
__device__ __half g_Wq[(size_t)HID_ * 3 * HID_];
__device__ __half g_Wd[(size_t)HID_ * HID_];
__device__ __half g_Atthi[(size_t)B_ * S_ * HID_];
__device__ __half g_Attlo[(size_t)B_ * S_ * HID_];

__device__ __half g_Qhi[(size_t)B_ * H_ * S_ * HS_];
__device__ __half g_Qlo[(size_t)B_ * H_ * S_ * HS_];
__device__ __half g_Kt[(size_t)B_ * H_ * HS_ * S_];
__device__ __half g_V[(size_t)B_ * H_ * S_ * HS_];

// ---------------- PTX helpers ----------------
__device__ __forceinline__ unsigned smem_u32(const void* p) {
    return (unsigned)__cvta_generic_to_shared(p);
}
__device__ __forceinline__ void cp16(unsigned s, const void* g) {
    asm volatile("cp.async.cg.shared.global [%0], [%1], 16;" :: "r"(s), "l"(g));
}
__device__ __forceinline__ void cp_commit() {
    asm volatile("cp.async.commit_group;");
}
__device__ __forceinline__ void cp_wait_1() {
    asm volatile("cp.async.wait_group 1;");
}
__device__ __forceinline__ void cp_wait_0() {
    asm volatile("cp.async.wait_group 0;");
}
__device__ __forceinline__ void ldm4(unsigned* r, unsigned a) {
    asm volatile("ldmatrix.sync.aligned.m8n8.x4.shared.b16 {%0,%1,%2,%3}, [%4];"
        : "=r"(r[0]), "=r"(r[1]), "=r"(r[2]), "=r"(r[3]) : "r"(a));
}
__device__ __forceinline__ void ldm4t(unsigned* r, unsigned a) {
    asm volatile("ldmatrix.sync.aligned.m8n8.x4.trans.shared.b16 {%0,%1,%2,%3}, [%4];"
        : "=r"(r[0]), "=r"(r[1]), "=r"(r[2]), "=r"(r[3]) : "r"(a));
}
__device__ __forceinline__ void mma16816(float* d, const unsigned* a, const unsigned* b) {
    asm volatile(
        "mma.sync.aligned.m16n8k16.row.col.f32.f16.f16.f32 "
        "{%0,%1,%2,%3},{%4,%5,%6,%7},{%8,%9},{%0,%1,%2,%3};"
        : "+f"(d[0]), "+f"(d[1]), "+f"(d[2]), "+f"(d[3])
        : "r"(a[0]), "r"(a[1]), "r"(a[2]), "r"(a[3]), "r"(b[0]), "r"(b[1]));
}

// ---------------- fp16 conversions ----------------
__global__ __launch_bounds__(256) void split2_fp16(
    const float* __restrict__ x, __half* __restrict__ hi,
    __half* __restrict__ lo, int n4)
{
    int i = blockIdx.x * 256 + threadIdx.x;
    if (i >= n4) return;
    float4 v = ((const float4*)x)[i];
    __half h0 = __float2half_rn(v.x), h1 = __float2half_rn(v.y);
    __half h2 = __float2half_rn(v.z), h3 = __float2half_rn(v.w);
    __half l0 = __float2half_rn(v.x - __half2float(h0));
    __half l1 = __float2half_rn(v.y - __half2float(h1));
    __half l2 = __float2half_rn(v.z - __half2float(h2));
    __half l3 = __float2half_rn(v.w - __half2float(h3));
    ((__half2*)hi)[i * 2 + 0] = __halves2half2(h0, h1);
    ((__half2*)hi)[i * 2 + 1] = __halves2half2(h2, h3);
    ((__half2*)lo)[i * 2 + 0] = __halves2half2(l0, l1);
    ((__half2*)lo)[i * 2 + 1] = __halves2half2(l2, l3);
}

__global__ __launch_bounds__(256) void split1_fp16(
    const float* __restrict__ x, __half* __restrict__ out, int n4)
{
    int i = blockIdx.x * 256 + threadIdx.x;
    if (i >= n4) return;
    float4 v = ((const float4*)x)[i];
    ((__half2*)out)[i * 2 + 0] = __floats2half2_rn(v.x, v.y);
    ((__half2*)out)[i * 2 + 1] = __floats2half2_rn(v.z, v.w);
}

// ---------------- fp16x2 GEMM: C = (Ahi+Alo) @ B + bias ----------------
// Block 128x128, BK=32, 256 threads, warp tile 64x32. 3-stage pipeline, 2 CTAs/SM.
#define BM 128
#define BN 128
#define BK 32
#define A_STRIDE 40
#define B_STRIDE 136
#define A_BYTES (128 * A_STRIDE * 2)
#define B_BYTES (32 * B_STRIDE * 2)
#define STAGE_BYTES (2 * A_BYTES + B_BYTES)       // 29184
#define GEMM_SMEM (3 * STAGE_BYTES)               // 87552

__device__ __forceinline__ void gemm_load_stage(
    unsigned base, int t,
    const __half* __restrict__ Ahi, const __half* __restrict__ Alo,
    const __half* __restrict__ Bs,
    int brow, int bcol, int k0, int K, int N)
{
    unsigned aHi = base;
    unsigned aLo = base + A_BYTES;
    unsigned bS  = base + 2 * A_BYTES;
#pragma unroll
    for (int i = 0; i < 2; i++) {
        int c = t + i * 256;
        int ar = c >> 2;
        int ak = (c & 3) * 8;
        size_t ga = (size_t)(brow + ar) * K + k0 + ak;
        unsigned sa = (unsigned)(ar * A_STRIDE + ak) * 2u;
        cp16(aHi + sa, Ahi + ga);
        cp16(aLo + sa, Alo + ga);
        int br = c >> 4;
        int nn = (c & 15) * 8;
        size_t gb = (size_t)(k0 + br) * N + bcol + nn;
        unsigned sb = (unsigned)(br * B_STRIDE + nn) * 2u;
        cp16(bS + sb, Bs + gb);
    }
    cp_commit();
}

__device__ __forceinline__ void gemm_compute_stage(
    unsigned base, int lane, int wm, int wn, float acc[4][4][4])
{
    unsigned aHi = base;
    unsigned bS  = base + 2 * A_BYTES;
#pragma unroll
    for (int kk = 0; kk < 32; kk += 16) {
        unsigned ah[4][4], al[4][4];
        const int arow = wm * 64 + (lane & 15);
        const int akc = kk + ((lane >> 4) << 3);
#pragma unroll
        for (int mt = 0; mt < 4; mt++) {
            unsigned ad = aHi + (unsigned)((arow + mt * 16) * A_STRIDE + akc) * 2u;
            ldm4(ah[mt], ad);
            ldm4(al[mt], ad + A_BYTES);
        }
        unsigned bh[2][4];
        const int krow = kk + (lane & 15);
        const int nc0 = wn * 32 + ((lane >> 4) << 3);
#pragma unroll
        for (int np = 0; np < 2; np++) {
            unsigned bd = bS + (unsigned)(krow * B_STRIDE + nc0 + np * 16) * 2u;
            ldm4t(bh[np], bd);
        }
#pragma unroll
        for (int mt = 0; mt < 4; mt++) {
#pragma unroll
            for (int np = 0; np < 2; np++) {
#pragma unroll
                for (int hlf = 0; hlf < 2; hlf++) {
                    float* d = acc[mt][np * 2 + hlf];
                    mma16816(d, ah[mt], &bh[np][hlf * 2]);
                    mma16816(d, al[mt], &bh[np][hlf * 2]);
                }
            }
        }
    }
}

__global__ __launch_bounds__(256) void gemm_fp16x2(
    const __half* __restrict__ Ahi, const __half* __restrict__ Alo,
    const __half* __restrict__ Bs,
    const float* __restrict__ bias, float* __restrict__ C,
    int M, int N, int K)
{
    extern __shared__ char dynsm[];
    const int t = threadIdx.x;
    const int lane = t & 31;
    const int warp = t >> 5;
    const int wm = warp >> 2;
    const int wn = warp & 3;
    const int brow = blockIdx.y * BM;
    const int bcol = blockIdx.x * BN;

    const unsigned smbase = smem_u32(dynsm);

    float acc[4][4][4];
#pragma unroll
    for (int i = 0; i < 4; i++)
#pragma unroll
        for (int j = 0; j < 4; j++)
#pragma unroll
            for (int k = 0; k < 4; k++) acc[i][j][k] = 0.f;

    const int niter = K / BK;
    // prologue: prefetch 2 stages
    gemm_load_stage(smbase, t, Ahi, Alo, Bs, brow, bcol, 0, K, N);
    gemm_load_stage(smbase + STAGE_BYTES, t, Ahi, Alo, Bs, brow, bcol, BK, K, N);

    int s_cur = 0, s_nxt = 2;   // stage indices mod 3
    for (int it = 0; it < niter; it++) {
        if (it + 1 < niter) cp_wait_1(); else cp_wait_0();
        __syncthreads();   // stage s_cur ready for ALL warps; compute(it-1) finished => stage s_nxt reusable
        if (it + 2 < niter) {
            gemm_load_stage(smbase + (unsigned)s_nxt * STAGE_BYTES, t,
                            Ahi, Alo, Bs, brow, bcol, (it + 2) * BK, K, N);
        }
        gemm_compute_stage(smbase + (unsigned)s_cur * STAGE_BYTES, lane, wm, wn, acc);
        s_cur = (s_cur + 1 == 3) ? 0 : s_cur + 1;
        s_nxt = (s_nxt + 1 == 3) ? 0 : s_nxt + 1;
    }

    const int g = lane >> 2;
    const int t2 = (lane & 3) * 2;
#pragma unroll
    for (int mt = 0; mt < 4; mt++) {
        int row = brow + wm * 64 + mt * 16 + g;
#pragma unroll
        for (int nt = 0; nt < 4; nt++) {
            int col = bcol + wn * 32 + nt * 8 + t2;
            float b0 = bias[col], b1 = bias[col + 1];
            float2 v0 = make_float2(acc[mt][nt][0] + b0, acc[mt][nt][1] + b1);
            float2 v1 = make_float2(acc[mt][nt][2] + b0, acc[mt][nt][3] + b1);
            *(float2*)(C + (size_t)row * N + col) = v0;
            *(float2*)(C + (size_t)(row + 8) * N + col) = v1;
        }
    }
}

// ---------------- rotary + split + scatter ----------------
#define ROT_SMEM (128 * 133 * 4)

__global__ __launch_bounds__(256) void rotary_split(
    const float* __restrict__ qkv, const int* __restrict__ pos,
    __half* __restrict__ Qhi, __half* __restrict__ Qlo,
    __half* __restrict__ Kt, __half* __restrict__ V)
{
    extern __shared__ char dynsm[];
    unsigned* ksm = (unsigned*)dynsm;

    const int t = threadIdx.x;
    const int s0 = blockIdx.x * 128;
    const int h = blockIdx.y, b = blockIdx.z;

#pragma unroll 4
    for (int i = 0; i < 64; i++) {
        int idx = t + i * 256;
        int d = idx & 127;
        int s = idx >> 7;
        const float* base = qkv + (size_t)(b * S_ + s0 + s) * (3 * HID_) + h * (3 * HS_);
        float q = base[d];
        float k = base[HS_ + d];
        float v = base[2 * HS_ + d];

        if (d < RD_) {
            float p = (float)pos[b * S_ + s0 + s];
            int fi = d & 15;
            float f = p * expf((float)(2 * fi) * (-1.0f / (float)RD_) * 9.210340371976184f);
            float c = cosf(f);
            float sn = sinf(f);
            int pd = (d < 16) ? d + 16 : d - 16;
            float sgn = (d < 16) ? -1.f : 1.f;
            float qp = base[pd];
            float kp = base[HS_ + pd];
            q = q * c + sgn * qp * sn;
            k = k * c + sgn * kp * sn;
        }

        size_t oi = ((size_t)(b * H_ + h) * S_ + s0 + s) * HS_ + d;
        __half qh = __float2half_rn(q);
        Qhi[oi] = qh;
        Qlo[oi] = __float2half_rn(q - __half2float(qh));
        V[oi] = __float2half_rn(v);

        __half kh = __float2half_rn(k);
        ksm[s * 133 + d] = (unsigned)__half_as_ushort(kh);
    }
    __syncthreads();

#pragma unroll 4
    for (int i = 0; i < 64; i++) {
        int idx = t + i * 256;
        int s = idx & 127;
        int d = idx >> 7;
        unsigned pk = ksm[s * 133 + d];
        size_t ko = ((size_t)(b * H_ + h) * HS_ + d) * S_ + s0 + s;
        Kt[ko] = __ushort_as_half((unsigned short)(pk & 0xffffu));
    }
}

// ---------------- tensor-core flash attention (causal, fp16 A-split, 3-stage) ----------------
#define FQ_STRIDE 136
#define FK_STRIDE 72
#define FV_STRIDE 136
#define FQ_BYTES (128 * FQ_STRIDE * 2)
#define FK_BYTES (128 * FK_STRIDE * 2)
#define FV_BYTES (64 * FV_STRIDE * 2)
#define FSTAGE   (FK_BYTES + FV_BYTES)              // 35840
#define FA_SMEM  (2 * FQ_BYTES + 3 * FSTAGE)        // 177152

__device__ __forceinline__ void fa_load_kv(
    unsigned base, int t,
    const __half* __restrict__ Kt, const __half* __restrict__ V,
    size_t bh, int k0)
{
    unsigned kS = base;
    unsigned vS = base + FK_BYTES;
#pragma unroll
    for (int i = 0; i < 4; i++) {
        int idx = t + i * 256;
        int kr = idx >> 3, kc = (idx & 7) * 8;
        size_t gk = bh + (size_t)kr * S_ + k0 + kc;
        unsigned sk = (unsigned)(kr * FK_STRIDE + kc) * 2u;
        cp16(kS + sk, Kt + gk);
        int vr = idx >> 4, vc = (idx & 15) * 8;
        size_t gv = bh + (size_t)(k0 + vr) * HS_ + vc;
        unsigned sv = (unsigned)(vr * FV_STRIDE + vc) * 2u;
        cp16(vS + sv, V + gv);
    }
}

__global__ __launch_bounds__(256) void flash_attn_mma(
    const __half* __restrict__ Qhi, const __half* __restrict__ Qlo,
    const __half* __restrict__ Kt,  const __half* __restrict__ V,
    const float* __restrict__ amask,
    __half* __restrict__ Outhi, __half* __restrict__ Outlo)
{
    extern __shared__ char dynsm[];
    const unsigned smb = smem_u32(dynsm);
    const unsigned sQh = smb;
    const unsigned sKV = smb + 2 * FQ_BYTES;

    const int t = threadIdx.x, lane = t & 31, w = t >> 5;
    const int qt = gridDim.x - 1 - blockIdx.x;
    const int q0 = qt * 128;
    const int h = blockIdx.y, b = blockIdx.z;
    const size_t bh = (size_t)(b * H_ + h) * S_ * HS_;

    const int nkt = 2 * (qt + 1);

    // prologue: Q + stage0 in group0; stage1 in group1
#pragma unroll
    for (int i = 0; i < 8; i++) {
        int idx = t + i * 256;
        int r = idx >> 4, c = (idx & 15) * 8;
        size_t g = bh + (size_t)(q0 + r) * HS_ + c;
        unsigned so = (unsigned)(r * FQ_STRIDE + c) * 2u;
        cp16(sQh + so, Qhi + g);
        cp16(sQh + FQ_BYTES + so, Qlo + g);
    }
    fa_load_kv(sKV, t, Kt, V, bh, 0);
    cp_commit();
    if (nkt > 1) {
        fa_load_kv(sKV + FSTAGE, t, Kt, V, bh, 64);
        cp_commit();
    }

    float Oa[16][4];
#pragma unroll
    for (int i = 0; i < 16; i++)
#pragma unroll
        for (int j = 0; j < 4; j++) Oa[i][j] = 0.f;

    float m0 = -1e30f, m1 = -1e30f, l0 = 0.f, l1 = 0.f;
    const float scale = 0.08838834764831845f;
    const int qrow0 = q0 + w * 16 + (lane >> 2);
    const int col_t = 2 * (lane & 3);

    int s_cur = 0, s_nxt = 2;
    for (int kt = 0; kt < nkt; kt++) {
        const int k0 = kt * 64;
        const unsigned stg = sKV + (unsigned)s_cur * FSTAGE;
        if (kt + 1 < nkt) cp_wait_1(); else cp_wait_0();
        __syncthreads();
        if (kt + 2 < nkt) {
            fa_load_kv(sKV + (unsigned)s_nxt * FSTAGE, t, Kt, V, bh, (kt + 2) * 64);
            cp_commit();
        }

        float Sa[8][4];
#pragma unroll
        for (int i = 0; i < 8; i++)
#pragma unroll
            for (int j = 0; j < 4; j++) Sa[i][j] = 0.f;

#pragma unroll
        for (int kk = 0; kk < 8; kk++) {
            unsigned ah[4], al[4];
            unsigned qa = sQh + (unsigned)((w * 16 + (lane & 15)) * FQ_STRIDE
                                           + kk * 16 + ((lane >> 4) << 3)) * 2u;
            ldm4(ah, qa);
            ldm4(al, qa + FQ_BYTES);
#pragma unroll
            for (int nb = 0; nb < 4; nb++) {
                unsigned kh[4];
                unsigned ka = stg + (unsigned)((kk * 16 + (lane & 15)) * FK_STRIDE
                                               + nb * 16 + ((lane >> 4) << 3)) * 2u;
                ldm4t(kh, ka);
#pragma unroll
                for (int hf = 0; hf < 2; hf++) {
                    mma16816(Sa[nb * 2 + hf], ah, &kh[hf * 2]);
                    mma16816(Sa[nb * 2 + hf], al, &kh[hf * 2]);
                }
            }
        }

        const bool needmask = (k0 + 63 > q0 + w * 16);
        float mc0 = -1e30f, mc1 = -1e30f;
#pragma unroll
        for (int j = 0; j < 8; j++) {
            int cb = k0 + j * 8 + col_t;
            float a0 = amask[(size_t)b * S_ + cb];
            float a1 = amask[(size_t)b * S_ + cb + 1];
            Sa[j][0] = Sa[j][0] * scale + a0;
            Sa[j][1] = Sa[j][1] * scale + a1;
            Sa[j][2] = Sa[j][2] * scale + a0;
            Sa[j][3] = Sa[j][3] * scale + a1;
            if (needmask) {
                if (cb > qrow0)         Sa[j][0] = -1e30f;
                if (cb + 1 > qrow0)     Sa[j][1] = -1e30f;
                if (cb > qrow0 + 8)     Sa[j][2] = -1e30f;
                if (cb + 1 > qrow0 + 8) Sa[j][3] = -1e30f;
            }
            mc0 = fmaxf(mc0, fmaxf(Sa[j][0], Sa[j][1]));
            mc1 = fmaxf(mc1, fmaxf(Sa[j][2], Sa[j][3]));
        }
        mc0 = fmaxf(mc0, __shfl_xor_sync(0xffffffffu, mc0, 1));
        mc0 = fmaxf(mc0, __shfl_xor_sync(0xffffffffu, mc0, 2));
        mc1 = fmaxf(mc1, __shfl_xor_sync(0xffffffffu, mc1, 1));
        mc1 = fmaxf(mc1, __shfl_xor_sync(0xffffffffu, mc1, 2));

        float mn0 = fmaxf(m0, mc0), mn1 = fmaxf(m1, mc1);
        float sf0 = __expf(m0 - mn0), sf1 = __expf(m1 - mn1);
        m0 = mn0; m1 = mn1;

        float ps0 = 0.f, ps1 = 0.f;
        unsigned phi[4][4], plo[4][4];
#pragma unroll
        for (int j = 0; j < 8; j++) {
            float p0 = __expf(Sa[j][0] - mn0);
            float p1 = __expf(Sa[j][1] - mn0);
            float p2 = __expf(Sa[j][2] - mn1);
            float p3 = __expf(Sa[j][3] - mn1);
            ps0 += p0 + p1;
            ps1 += p2 + p3;
            __half2 h01 = __floats2half2_rn(p0, p1);
            __half2 h23 = __floats2half2_rn(p2, p3);
            float2 f01 = __half22float2(h01);
            float2 f23 = __half22float2(h23);
            __half2 l01 = __floats2half2_rn(p0 - f01.x, p1 - f01.y);
            __half2 l23 = __floats2half2_rn(p2 - f23.x, p3 - f23.y);
            int kf = j >> 1, q = (j & 1) * 2;
            phi[kf][q + 0] = *reinterpret_cast<unsigned*>(&h01);
            phi[kf][q + 1] = *reinterpret_cast<unsigned*>(&h23);
            plo[kf][q + 0] = *reinterpret_cast<unsigned*>(&l01);
            plo[kf][q + 1] = *reinterpret_cast<unsigned*>(&l23);
        }
        ps0 += __shfl_xor_sync(0xffffffffu, ps0, 1);
        ps0 += __shfl_xor_sync(0xffffffffu, ps0, 2);
        ps1 += __shfl_xor_sync(0xffffffffu, ps1, 1);
        ps1 += __shfl_xor_sync(0xffffffffu, ps1, 2);
        l0 = l0 * sf0 + ps0;
        l1 = l1 * sf1 + ps1;

#pragma unroll
        for (int nb = 0; nb < 16; nb++) {
            Oa[nb][0] *= sf0; Oa[nb][1] *= sf0;
            Oa[nb][2] *= sf1; Oa[nb][3] *= sf1;
        }

        const unsigned vSb = stg + FK_BYTES;
#pragma unroll
        for (int kf = 0; kf < 4; kf++) {
#pragma unroll
            for (int nb = 0; nb < 8; nb++) {
                unsigned vh[4];
                unsigned va = vSb + (unsigned)((kf * 16 + (lane & 15)) * FV_STRIDE
                                               + nb * 16 + ((lane >> 4) << 3)) * 2u;
                ldm4t(vh, va);
#pragma unroll
                for (int hf = 0; hf < 2; hf++) {
                    mma16816(Oa[nb * 2 + hf], phi[kf], &vh[hf * 2]);
                    mma16816(Oa[nb * 2 + hf], plo[kf], &vh[hf * 2]);
                }
            }
        }
        s_cur = (s_cur + 1 == 3) ? 0 : s_cur + 1;
        s_nxt = (s_nxt + 1 == 3) ? 0 : s_nxt + 1;
    }

    float rl0 = 1.0f / l0, rl1 = 1.0f / l1;
#pragma unroll
    for (int nb = 0; nb < 16; nb++) {
        int c = nb * 8 + col_t;
        float v0 = Oa[nb][0] * rl0, v1 = Oa[nb][1] * rl0;
        float v2 = Oa[nb][2] * rl1, v3 = Oa[nb][3] * rl1;
        __half2 h01 = __floats2half2_rn(v0, v1);
        __half2 h23 = __floats2half2_rn(v2, v3);
        float2 f01 = __half22float2(h01);
        float2 f23 = __half22float2(h23);
        __half2 l01 = __floats2half2_rn(v0 - f01.x, v1 - f01.y);
        __half2 l23 = __floats2half2_rn(v2 - f23.x, v3 - f23.y);
        size_t o0 = (size_t)(b * S_ + qrow0) * HID_ + h * HS_ + c;
        size_t o1 = o0 + (size_t)8 * HID_;
        *reinterpret_cast<__half2*>(Outhi + o0) = h01;
        *reinterpret_cast<__half2*>(Outhi + o1) = h23;
        *reinterpret_cast<__half2*>(Outlo + o0) = l01;
        *reinterpret_cast<__half2*>(Outlo + o1) = l23;
    }
}

// ---------------- launch ----------------
extern "C" void kernel_launch(void* const* d_in, const int* in_sizes, int n_in,
                              void* d_out, int out_size) {
    const float* hidden = (const float*)d_in[0];
    const float* amask  = (const float*)d_in[1];
    const int*   pos    = (const int*)d_in[2];
    const float* Wqkv   = (const float*)d_in[3];
    const float* bqkv   = (const float*)d_in[4];
    const float* Wd     = (const float*)d_in[5];
    const float* bd     = (const float*)d_in[6];
    float* out = (float*)d_out;

    float* qkv;
    __half *Ahi, *Alo, *Wq, *Wdh, *Atthi, *Attlo;
    __half *Qhi, *Qlo, *Kt, *Vp;
    cudaGetSymbolAddress((void**)&qkv, g_qkv);
    cudaGetSymbolAddress((void**)&Ahi, g_Ahi);
    cudaGetSymbolAddress((void**)&Alo, g_Alo);
    cudaGetSymbolAddress((void**)&Wq,  g_Wq);
    cudaGetSymbolAddress((void**)&Wdh, g_Wd);
    cudaGetSymbolAddress((void**)&Atthi, g_Atthi);
    cudaGetSymbolAddress((void**)&Attlo, g_Attlo);
    cudaGetSymbolAddress((void**)&Qhi, g_Qhi);
    cudaGetSymbolAddress((void**)&Qlo, g_Qlo);
    cudaGetSymbolAddress((void**)&Kt,  g_Kt);
    cudaGetSymbolAddress((void**)&Vp,  g_V);

    cudaFuncSetAttribute(gemm_fp16x2, cudaFuncAttributeMaxDynamicSharedMemorySize, GEMM_SMEM);
    cudaFuncSetAttribute(rotary_split, cudaFuncAttributeMaxDynamicSharedMemorySize, ROT_SMEM);
    cudaFuncSetAttribute(flash_attn_mma, cudaFuncAttributeMaxDynamicSharedMemorySize, FA_SMEM);

    // 0) convert: hidden -> fp16 hi/lo; weights -> fp16 single
    split2_fp16<<<(B_ * S_ * HID_ / 4 + 255) / 256, 256>>>(hidden, Ahi, Alo, B_ * S_ * HID_ / 4);
    split1_fp16<<<(HID_ * 3 * HID_ / 4 + 255) / 256, 256>>>(Wqkv, Wq, HID_ * 3 * HID_ / 4);
    split1_fp16<<<(HID_ * HID_ / 4 + 255) / 256, 256>>>(Wd, Wdh, HID_ * HID_ / 4);

    // 1) QKV GEMM (fp16 A-split, 2 passes) + bias
    gemm_fp16x2<<<dim3((3 * HID_) / BN, (B_ * S_) / BM), 256, GEMM_SMEM>>>(
        Ahi, Alo, Wq, bqkv, qkv, B_ * S_, 3 * HID_, HID_);

    // 2) rotary + fp16 split + K transpose
    rotary_split<<<dim3(S_ / 128, H_, B_), 256, ROT_SMEM>>>(
        qkv, pos, Qhi, Qlo, Kt, Vp);

    // 3) tensor-core causal flash attention
    flash_attn_mma<<<dim3(S_ / 128, H_, B_), 256, FA_SMEM>>>(
        Qhi, Qlo, Kt, Vp, amask, Atthi, Attlo);

    // 4) dense GEMM (fp16 A-split, 2 passes) + bias
    gemm_fp16x2<<<dim3(HID_ / BN, (B_ * S_) / BM), 256, GEMM_SMEM>>>(
        Atthi, Attlo, Wdh, bd, out, B_ * S_, HID_, HID_);
}

// round 12
// speedup vs baseline: 1.1396x; 1.1396x over previous
#include <cuda_runtime.h>
#include <cuda_fp16.h>
#include <math.h>
#include <stdint.h>
#include <stddef.h>

#define B_   2
#define S_   2048
#define HID_ 2048
#define H_   16
#define HS_  128
#define RD_  32

// ---------------- scratch (device globals) ----------------
__device__ float g_qkv[(size_t)B_ * S_ * 3 * HID_];

__device__ __half g_Ahi[(size_t)B_ * S_ * HID_];
__device__ __half g_Alo[(size_t)B_ * S_ * HID_];
__device__ __half g_Wq[(size_t)HID_ * 3 * HID_];
__device__ __half g_Wd[(size_t)HID_ * HID_];
__device__ __half g_Att[(size_t)B_ * S_ * HID_];     // attn out, fp16 single

__device__ __half g_Qhi[(size_t)B_ * H_ * S_ * HS_];
__device__ __half g_Qlo[(size_t)B_ * H_ * S_ * HS_];
__device__ __half g_Kt[(size_t)B_ * H_ * HS_ * S_];
__device__ __half g_V[(size_t)B_ * H_ * S_ * HS_];

// ---------------- PTX helpers ----------------
__device__ __forceinline__ unsigned smem_u32(const void* p) {
    return (unsigned)__cvta_generic_to_shared(p);
}
__device__ __forceinline__ void cp16(unsigned s, const void* g) {
    asm volatile("cp.async.cg.shared.global [%0], [%1], 16;" :: "r"(s), "l"(g));
}
__device__ __forceinline__ void cp_commit() {
    asm volatile("cp.async.commit_group;");
}
__device__ __forceinline__ void cp_wait_1() {
    asm volatile("cp.async.wait_group 1;");
}
__device__ __forceinline__ void cp_wait_0() {
    asm volatile("cp.async.wait_group 0;");
}
__device__ __forceinline__ void ldm4(unsigned* r, unsigned a) {
    asm volatile("ldmatrix.sync.aligned.m8n8.x4.shared.b16 {%0,%1,%2,%3}, [%4];"
        : "=r"(r[0]), "=r"(r[1]), "=r"(r[2]), "=r"(r[3]) : "r"(a));
}
__device__ __forceinline__ void ldm4t(unsigned* r, unsigned a) {
    asm volatile("ldmatrix.sync.aligned.m8n8.x4.trans.shared.b16 {%0,%1,%2,%3}, [%4];"
        : "=r"(r[0]), "=r"(r[1]), "=r"(r[2]), "=r"(r[3]) : "r"(a));
}
__device__ __forceinline__ void mma16816(float* d, const unsigned* a, const unsigned* b) {
    asm volatile(
        "mma.sync.aligned.m16n8k16.row.col.f32.f16.f16.f32 "
        "{%0,%1,%2,%3},{%4,%5,%6,%7},{%8,%9},{%0,%1,%2,%3};"
        : "+f"(d[0]), "+f"(d[1]), "+f"(d[2]), "+f"(d[3])
        : "r"(a[0]), "r"(a[1]), "r"(a[2]), "r"(a[3]), "r"(b[0]), "r"(b[1]));
}

// ---------------- fp16 conversions ----------------
__global__ __launch_bounds__(256) void split2_fp16(
    const float* __restrict__ x, __half* __restrict__ hi,
    __half* __restrict__ lo, int n4)
{
    int i = blockIdx.x * 256 + threadIdx.x;
    if (i >= n4) return;
    float4 v = ((const float4*)x)[i];
    __half h0 = __float2half_rn(v.x), h1 = __float2half_rn(v.y);
    __half h2 = __float2half_rn(v.z), h3 = __float2half_rn(v.w);
    __half l0 = __float2half_rn(v.x - __half2float(h0));
    __half l1 = __float2half_rn(v.y - __half2float(h1));
    __half l2 = __float2half_rn(v.z - __half2float(h2));
    __half l3 = __float2half_rn(v.w - __half2float(h3));
    ((__half2*)hi)[i * 2 + 0] = __halves2half2(h0, h1);
    ((__half2*)hi)[i * 2 + 1] = __halves2half2(h2, h3);
    ((__half2*)lo)[i * 2 + 0] = __halves2half2(l0, l1);
    ((__half2*)lo)[i * 2 + 1] = __halves2half2(l2, l3);
}

__global__ __launch_bounds__(256) void split1_fp16(
    const float* __restrict__ x, __half* __restrict__ out, int n4)
{
    int i = blockIdx.x * 256 + threadIdx.x;
    if (i >= n4) return;
    float4 v = ((const float4*)x)[i];
    ((__half2*)out)[i * 2 + 0] = __floats2half2_rn(v.x, v.y);
    ((__half2*)out)[i * 2 + 1] = __floats2half2_rn(v.z, v.w);
}

// ---------------- shared GEMM tile config ----------------
#define BM 128
#define BN 128
#define BK 32
#define A_STRIDE 40
#define B_STRIDE 136
#define A_BYTES (128 * A_STRIDE * 2)
#define B_BYTES (32 * B_STRIDE * 2)

// ================= fp16x2 GEMM (A hi/lo, 2 passes): C = (Ahi+Alo) @ B + bias =================
#define STAGE2_BYTES (2 * A_BYTES + B_BYTES)       // 29184
#define GEMM2_SMEM (2 * STAGE2_BYTES)              // 58368

__device__ __forceinline__ void gemm2_load_stage(
    unsigned base, int t,
    const __half* __restrict__ Ahi, const __half* __restrict__ Alo,
    const __half* __restrict__ Bs,
    int brow, int bcol, int k0, int K, int N)
{
    unsigned aHi = base;
    unsigned aLo = base + A_BYTES;
    unsigned bS  = base + 2 * A_BYTES;
#pragma unroll
    for (int i = 0; i < 2; i++) {
        int c = t + i * 256;
        int ar = c >> 2;
        int ak = (c & 3) * 8;
        size_t ga = (size_t)(brow + ar) * K + k0 + ak;
        unsigned sa = (unsigned)(ar * A_STRIDE + ak) * 2u;
        cp16(aHi + sa, Ahi + ga);
        cp16(aLo + sa, Alo + ga);
        int br = c >> 4;
        int nn = (c & 15) * 8;
        size_t gb = (size_t)(k0 + br) * N + bcol + nn;
        unsigned sb = (unsigned)(br * B_STRIDE + nn) * 2u;
        cp16(bS + sb, Bs + gb);
    }
    cp_commit();
}

__device__ __forceinline__ void gemm2_compute_stage(
    unsigned base, int lane, int wm, int wn, float acc[4][4][4])
{
    unsigned aHi = base;
    unsigned bS  = base + 2 * A_BYTES;
#pragma unroll
    for (int kk = 0; kk < 32; kk += 16) {
        unsigned ah[4][4], al[4][4];
        const int arow = wm * 64 + (lane & 15);
        const int akc = kk + ((lane >> 4) << 3);
#pragma unroll
        for (int mt = 0; mt < 4; mt++) {
            unsigned ad = aHi + (unsigned)((arow + mt * 16) * A_STRIDE + akc) * 2u;
            ldm4(ah[mt], ad);
            ldm4(al[mt], ad + A_BYTES);
        }
        unsigned bh[2][4];
        const int krow = kk + (lane & 15);
        const int nc0 = wn * 32 + ((lane >> 4) << 3);
#pragma unroll
        for (int np = 0; np < 2; np++) {
            unsigned bd = bS + (unsigned)(krow * B_STRIDE + nc0 + np * 16) * 2u;
            ldm4t(bh[np], bd);
        }
#pragma unroll
        for (int mt = 0; mt < 4; mt++) {
#pragma unroll
            for (int np = 0; np < 2; np++) {
#pragma unroll
                for (int hlf = 0; hlf < 2; hlf++) {
                    float* d = acc[mt][np * 2 + hlf];
                    mma16816(d, ah[mt], &bh[np][hlf * 2]);
                    mma16816(d, al[mt], &bh[np][hlf * 2]);
                }
            }
        }
    }
}

__global__ __launch_bounds__(256) void gemm_fp16x2(
    const __half* __restrict__ Ahi, const __half* __restrict__ Alo,
    const __half* __restrict__ Bs,
    const float* __restrict__ bias, float* __restrict__ C,
    int M, int N, int K)
{
    extern __shared__ char dynsm[];
    const int t = threadIdx.x;
    const int lane = t & 31;
    const int warp = t >> 5;
    const int wm = warp >> 2;
    const int wn = warp & 3;
    const int brow = blockIdx.y * BM;
    const int bcol = blockIdx.x * BN;

    const unsigned smbase = smem_u32(dynsm);

    float acc[4][4][4];
#pragma unroll
    for (int i = 0; i < 4; i++)
#pragma unroll
        for (int j = 0; j < 4; j++)
#pragma unroll
            for (int k = 0; k < 4; k++) acc[i][j][k] = 0.f;

    const int niter = K / BK;
    gemm2_load_stage(smbase, t, Ahi, Alo, Bs, brow, bcol, 0, K, N);
    for (int it = 0; it < niter; it++) {
        if (it + 1 < niter) {
            gemm2_load_stage(smbase + ((it + 1) & 1) * STAGE2_BYTES, t,
                             Ahi, Alo, Bs, brow, bcol, (it + 1) * BK, K, N);
            cp_wait_1();
        } else {
            cp_wait_0();
        }
        __syncthreads();
        gemm2_compute_stage(smbase + (it & 1) * STAGE2_BYTES, lane, wm, wn, acc);
        __syncthreads();
    }

    const int g = lane >> 2;
    const int t2 = (lane & 3) * 2;
#pragma unroll
    for (int mt = 0; mt < 4; mt++) {
        int row = brow + wm * 64 + mt * 16 + g;
#pragma unroll
        for (int nt = 0; nt < 4; nt++) {
            int col = bcol + wn * 32 + nt * 8 + t2;
            float b0 = bias[col], b1 = bias[col + 1];
            float2 v0 = make_float2(acc[mt][nt][0] + b0, acc[mt][nt][1] + b1);
            float2 v1 = make_float2(acc[mt][nt][2] + b0, acc[mt][nt][3] + b1);
            *(float2*)(C + (size_t)row * N + col) = v0;
            *(float2*)(C + (size_t)(row + 8) * N + col) = v1;
        }
    }
}

// ================= fp16x1 GEMM (single pass): C = A @ B + bias =================
#define STAGE1_BYTES (A_BYTES + B_BYTES)           // 18944
#define GEMM1_SMEM (2 * STAGE1_BYTES)              // 37888

__device__ __forceinline__ void gemm1_load_stage(
    unsigned base, int t,
    const __half* __restrict__ As, const __half* __restrict__ Bs,
    int brow, int bcol, int k0, int K, int N)
{
    unsigned aS = base;
    unsigned bS = base + A_BYTES;
#pragma unroll
    for (int i = 0; i < 2; i++) {
        int c = t + i * 256;
        int ar = c >> 2;
        int ak = (c & 3) * 8;
        size_t ga = (size_t)(brow + ar) * K + k0 + ak;
        unsigned sa = (unsigned)(ar * A_STRIDE + ak) * 2u;
        cp16(aS + sa, As + ga);
        int br = c >> 4;
        int nn = (c & 15) * 8;
        size_t gb = (size_t)(k0 + br) * N + bcol + nn;
        unsigned sb = (unsigned)(br * B_STRIDE + nn) * 2u;
        cp16(bS + sb, Bs + gb);
    }
    cp_commit();
}

__device__ __forceinline__ void gemm1_compute_stage(
    unsigned base, int lane, int wm, int wn, float acc[4][4][4])
{
    unsigned aS = base;
    unsigned bS = base + A_BYTES;
#pragma unroll
    for (int kk = 0; kk < 32; kk += 16) {
        unsigned ah[4][4];
        const int arow = wm * 64 + (lane & 15);
        const int akc = kk + ((lane >> 4) << 3);
#pragma unroll
        for (int mt = 0; mt < 4; mt++) {
            unsigned ad = aS + (unsigned)((arow + mt * 16) * A_STRIDE + akc) * 2u;
            ldm4(ah[mt], ad);
        }
        unsigned bh[2][4];
        const int krow = kk + (lane & 15);
        const int nc0 = wn * 32 + ((lane >> 4) << 3);
#pragma unroll
        for (int np = 0; np < 2; np++) {
            unsigned bd = bS + (unsigned)(krow * B_STRIDE + nc0 + np * 16) * 2u;
            ldm4t(bh[np], bd);
        }
#pragma unroll
        for (int mt = 0; mt < 4; mt++)
#pragma unroll
            for (int np = 0; np < 2; np++)
#pragma unroll
                for (int hlf = 0; hlf < 2; hlf++)
                    mma16816(acc[mt][np * 2 + hlf], ah[mt], &bh[np][hlf * 2]);
    }
}

__global__ __launch_bounds__(256) void gemm_fp16x1(
    const __half* __restrict__ As, const __half* __restrict__ Bs,
    const float* __restrict__ bias, float* __restrict__ C,
    int M, int N, int K)
{
    extern __shared__ char dynsm[];
    const int t = threadIdx.x;
    const int lane = t & 31;
    const int warp = t >> 5;
    const int wm = warp >> 2;
    const int wn = warp & 3;
    const int brow = blockIdx.y * BM;
    const int bcol = blockIdx.x * BN;

    const unsigned smbase = smem_u32(dynsm);

    float acc[4][4][4];
#pragma unroll
    for (int i = 0; i < 4; i++)
#pragma unroll
        for (int j = 0; j < 4; j++)
#pragma unroll
            for (int k = 0; k < 4; k++) acc[i][j][k] = 0.f;

    const int niter = K / BK;
    gemm1_load_stage(smbase, t, As, Bs, brow, bcol, 0, K, N);
    for (int it = 0; it < niter; it++) {
        if (it + 1 < niter) {
            gemm1_load_stage(smbase + ((it + 1) & 1) * STAGE1_BYTES, t,
                             As, Bs, brow, bcol, (it + 1) * BK, K, N);
            cp_wait_1();
        } else {
            cp_wait_0();
        }
        __syncthreads();
        gemm1_compute_stage(smbase + (it & 1) * STAGE1_BYTES, lane, wm, wn, acc);
        __syncthreads();
    }

    const int g = lane >> 2;
    const int t2 = (lane & 3) * 2;
#pragma unroll
    for (int mt = 0; mt < 4; mt++) {
        int row = brow + wm * 64 + mt * 16 + g;
#pragma unroll
        for (int nt = 0; nt < 4; nt++) {
            int col = bcol + wn * 32 + nt * 8 + t2;
            float b0 = bias[col], b1 = bias[col + 1];
            float2 v0 = make_float2(acc[mt][nt][0] + b0, acc[mt][nt][1] + b1);
            float2 v1 = make_float2(acc[mt][nt][2] + b0, acc[mt][nt][3] + b1);
            *(float2*)(C + (size_t)row * N + col) = v0;
            *(float2*)(C + (size_t)(row + 8) * N + col) = v1;
        }
    }
}

// ---------------- rotary + split + scatter ----------------
#define ROT_SMEM (128 * 133 * 4)

__global__ __launch_bounds__(256) void rotary_split(
    const float* __restrict__ qkv, const int* __restrict__ pos,
    __half* __restrict__ Qhi, __half* __restrict__ Qlo,
    __half* __restrict__ Kt, __half* __restrict__ V)
{
    extern __shared__ char dynsm[];
    unsigned* ksm = (unsigned*)dynsm;

    const int t = threadIdx.x;
    const int s0 = blockIdx.x * 128;
    const int h = blockIdx.y, b = blockIdx.z;

#pragma unroll 4
    for (int i = 0; i < 64; i++) {
        int idx = t + i * 256;
        int d = idx & 127;
        int s = idx >> 7;
        const float* base = qkv + (size_t)(b * S_ + s0 + s) * (3 * HID_) + h * (3 * HS_);
        float q = base[d];
        float k = base[HS_ + d];
        float v = base[2 * HS_ + d];

        if (d < RD_) {
            float p = (float)pos[b * S_ + s0 + s];
            int fi = d & 15;
            float f = p * expf((float)(2 * fi) * (-1.0f / (float)RD_) * 9.210340371976184f);
            float c = cosf(f);
            float sn = sinf(f);
            int pd = (d < 16) ? d + 16 : d - 16;
            float sgn = (d < 16) ? -1.f : 1.f;
            float qp = base[pd];
            float kp = base[HS_ + pd];
            q = q * c + sgn * qp * sn;
            k = k * c + sgn * kp * sn;
        }

        size_t oi = ((size_t)(b * H_ + h) * S_ + s0 + s) * HS_ + d;
        __half qh = __float2half_rn(q);
        Qhi[oi] = qh;
        Qlo[oi] = __float2half_rn(q - __half2float(qh));
        V[oi] = __float2half_rn(v);

        __half kh = __float2half_rn(k);
        ksm[s * 133 + d] = (unsigned)__half_as_ushort(kh);
    }
    __syncthreads();

#pragma unroll 4
    for (int i = 0; i < 64; i++) {
        int idx = t + i * 256;
        int s = idx & 127;
        int d = idx >> 7;
        unsigned pk = ksm[s * 133 + d];
        size_t ko = ((size_t)(b * H_ + h) * HS_ + d) * S_ + s0 + s;
        Kt[ko] = __ushort_as_half((unsigned short)(pk & 0xffffu));
    }
}

// ---------------- tensor-core flash attention (causal; QK 2-pass, PV 1-pass) ----------------
#define FQ_STRIDE 136
#define FK_STRIDE 72
#define FV_STRIDE 136
#define FQ_BYTES (128 * FQ_STRIDE * 2)
#define FK_BYTES (128 * FK_STRIDE * 2)
#define FV_BYTES (64 * FV_STRIDE * 2)
#define FSTAGE   (FK_BYTES + FV_BYTES)
#define FA_SMEM  (2 * FQ_BYTES + 2 * FSTAGE)

__device__ __forceinline__ void fa_load_kv(
    unsigned base, int t,
    const __half* __restrict__ Kt, const __half* __restrict__ V,
    size_t bh, int k0)
{
    unsigned kS = base;
    unsigned vS = base + FK_BYTES;
#pragma unroll
    for (int i = 0; i < 4; i++) {
        int idx = t + i * 256;
        int kr = idx >> 3, kc = (idx & 7) * 8;
        size_t gk = bh + (size_t)kr * S_ + k0 + kc;
        unsigned sk = (unsigned)(kr * FK_STRIDE + kc) * 2u;
        cp16(kS + sk, Kt + gk);
        int vr = idx >> 4, vc = (idx & 15) * 8;
        size_t gv = bh + (size_t)(k0 + vr) * HS_ + vc;
        unsigned sv = (unsigned)(vr * FV_STRIDE + vc) * 2u;
        cp16(vS + sv, V + gv);
    }
}

__global__ __launch_bounds__(256) void flash_attn_mma(
    const __half* __restrict__ Qhi, const __half* __restrict__ Qlo,
    const __half* __restrict__ Kt,  const __half* __restrict__ V,
    const float* __restrict__ amask,
    __half* __restrict__ Out)
{
    extern __shared__ char dynsm[];
    const unsigned smb = smem_u32(dynsm);
    const unsigned sQh = smb;

    const int t = threadIdx.x, lane = t & 31, w = t >> 5;
    const int qt = gridDim.x - 1 - blockIdx.x;
    const int q0 = qt * 128;
    const int h = blockIdx.y, b = blockIdx.z;
    const size_t bh = (size_t)(b * H_ + h) * S_ * HS_;

#pragma unroll
    for (int i = 0; i < 8; i++) {
        int idx = t + i * 256;
        int r = idx >> 4, c = (idx & 15) * 8;
        size_t g = bh + (size_t)(q0 + r) * HS_ + c;
        unsigned so = (unsigned)(r * FQ_STRIDE + c) * 2u;
        cp16(sQh + so, Qhi + g);
        cp16(sQh + FQ_BYTES + so, Qlo + g);
    }
    fa_load_kv(smb + 2 * FQ_BYTES, t, Kt, V, bh, 0);
    cp_commit();

    float Oa[16][4];
#pragma unroll
    for (int i = 0; i < 16; i++)
#pragma unroll
        for (int j = 0; j < 4; j++) Oa[i][j] = 0.f;

    float m0 = -1e30f, m1 = -1e30f, l0 = 0.f, l1 = 0.f;
    const int nkt = 2 * (qt + 1);
    const float scale = 0.08838834764831845f;
    const int qrow0 = q0 + w * 16 + (lane >> 2);
    const int col_t = 2 * (lane & 3);

    for (int kt = 0; kt < nkt; kt++) {
        const int k0 = kt * 64;
        const unsigned stg = smb + 2 * FQ_BYTES + (kt & 1) * FSTAGE;
        if (kt + 1 < nkt) {
            fa_load_kv(smb + 2 * FQ_BYTES + ((kt + 1) & 1) * FSTAGE, t,
                       Kt, V, bh, (kt + 1) * 64);
            cp_commit();
            cp_wait_1();
        } else {
            cp_wait_0();
        }
        __syncthreads();

        float Sa[8][4];
#pragma unroll
        for (int i = 0; i < 8; i++)
#pragma unroll
            for (int j = 0; j < 4; j++) Sa[i][j] = 0.f;

#pragma unroll
        for (int kk = 0; kk < 8; kk++) {
            unsigned ah[4], al[4];
            unsigned qa = sQh + (unsigned)((w * 16 + (lane & 15)) * FQ_STRIDE
                                           + kk * 16 + ((lane >> 4) << 3)) * 2u;
            ldm4(ah, qa);
            ldm4(al, qa + FQ_BYTES);
#pragma unroll
            for (int nb = 0; nb < 4; nb++) {
                unsigned kh[4];
                unsigned ka = stg + (unsigned)((kk * 16 + (lane & 15)) * FK_STRIDE
                                               + nb * 16 + ((lane >> 4) << 3)) * 2u;
                ldm4t(kh, ka);
#pragma unroll
                for (int hf = 0; hf < 2; hf++) {
                    mma16816(Sa[nb * 2 + hf], ah, &kh[hf * 2]);
                    mma16816(Sa[nb * 2 + hf], al, &kh[hf * 2]);
                }
            }
        }

        const bool needmask = (k0 + 63 > q0 + w * 16);
        float mc0 = -1e30f, mc1 = -1e30f;
#pragma unroll
        for (int j = 0; j < 8; j++) {
            int cb = k0 + j * 8 + col_t;
            float a0 = amask[(size_t)b * S_ + cb];
            float a1 = amask[(size_t)b * S_ + cb + 1];
            Sa[j][0] = Sa[j][0] * scale + a0;
            Sa[j][1] = Sa[j][1] * scale + a1;
            Sa[j][2] = Sa[j][2] * scale + a0;
            Sa[j][3] = Sa[j][3] * scale + a1;
            if (needmask) {
                if (cb > qrow0)         Sa[j][0] = -1e30f;
                if (cb + 1 > qrow0)     Sa[j][1] = -1e30f;
                if (cb > qrow0 + 8)     Sa[j][2] = -1e30f;
                if (cb + 1 > qrow0 + 8) Sa[j][3] = -1e30f;
            }
            mc0 = fmaxf(mc0, fmaxf(Sa[j][0], Sa[j][1]));
            mc1 = fmaxf(mc1, fmaxf(Sa[j][2], Sa[j][3]));
        }
        mc0 = fmaxf(mc0, __shfl_xor_sync(0xffffffffu, mc0, 1));
        mc0 = fmaxf(mc0, __shfl_xor_sync(0xffffffffu, mc0, 2));
        mc1 = fmaxf(mc1, __shfl_xor_sync(0xffffffffu, mc1, 1));
        mc1 = fmaxf(mc1, __shfl_xor_sync(0xffffffffu, mc1, 2));

        float mn0 = fmaxf(m0, mc0), mn1 = fmaxf(m1, mc1);
        float sf0 = __expf(m0 - mn0), sf1 = __expf(m1 - mn1);
        m0 = mn0; m1 = mn1;

        float ps0 = 0.f, ps1 = 0.f;
        unsigned phi[4][4];
#pragma unroll
        for (int j = 0; j < 8; j++) {
            float p0 = __expf(Sa[j][0] - mn0);
            float p1 = __expf(Sa[j][1] - mn0);
            float p2 = __expf(Sa[j][2] - mn1);
            float p3 = __expf(Sa[j][3] - mn1);
            ps0 += p0 + p1;
            ps1 += p2 + p3;
            __half2 h01 = __floats2half2_rn(p0, p1);
            __half2 h23 = __floats2half2_rn(p2, p3);
            int kf = j >> 1, q = (j & 1) * 2;
            phi[kf][q + 0] = *reinterpret_cast<unsigned*>(&h01);
            phi[kf][q + 1] = *reinterpret_cast<unsigned*>(&h23);
        }
        ps0 += __shfl_xor_sync(0xffffffffu, ps0, 1);
        ps0 += __shfl_xor_sync(0xffffffffu, ps0, 2);
        ps1 += __shfl_xor_sync(0xffffffffu, ps1, 1);
        ps1 += __shfl_xor_sync(0xffffffffu, ps1, 2);
        l0 = l0 * sf0 + ps0;
        l1 = l1 * sf1 + ps1;

#pragma unroll
        for (int nb = 0; nb < 16; nb++) {
            Oa[nb][0] *= sf0; Oa[nb][1] *= sf0;
            Oa[nb][2] *= sf1; Oa[nb][3] *= sf1;
        }

        const unsigned vSb = stg + FK_BYTES;
#pragma unroll
        for (int kf = 0; kf < 4; kf++) {
#pragma unroll
            for (int nb = 0; nb < 8; nb++) {
                unsigned vh[4];
                unsigned va = vSb + (unsigned)((kf * 16 + (lane & 15)) * FV_STRIDE
                                               + nb * 16 + ((lane >> 4) << 3)) * 2u;
                ldm4t(vh, va);
#pragma unroll
                for (int hf = 0; hf < 2; hf++)
                    mma16816(Oa[nb * 2 + hf], phi[kf], &vh[hf * 2]);
            }
        }
        __syncthreads();
    }

    float rl0 = 1.0f / l0, rl1 = 1.0f / l1;
#pragma unroll
    for (int nb = 0; nb < 16; nb++) {
        int c = nb * 8 + col_t;
        __half2 h01 = __floats2half2_rn(Oa[nb][0] * rl0, Oa[nb][1] * rl0);
        __half2 h23 = __floats2half2_rn(Oa[nb][2] * rl1, Oa[nb][3] * rl1);
        size_t o0 = (size_t)(b * S_ + qrow0) * HID_ + h * HS_ + c;
        size_t o1 = o0 + (size_t)8 * HID_;
        *reinterpret_cast<__half2*>(Out + o0) = h01;
        *reinterpret_cast<__half2*>(Out + o1) = h23;
    }
}

// ---------------- launch ----------------
extern "C" void kernel_launch(void* const* d_in, const int* in_sizes, int n_in,
                              void* d_out, int out_size) {
    const float* hidden = (const float*)d_in[0];
    const float* amask  = (const float*)d_in[1];
    const int*   pos    = (const int*)d_in[2];
    const float* Wqkv   = (const float*)d_in[3];
    const float* bqkv   = (const float*)d_in[4];
    const float* Wd     = (const float*)d_in[5];
    const float* bd     = (const float*)d_in[6];
    float* out = (float*)d_out;

    float* qkv;
    __half *Ahi, *Alo, *Wq, *Wdh, *Att;
    __half *Qhi, *Qlo, *Kt, *Vp;
    cudaGetSymbolAddress((void**)&qkv, g_qkv);
    cudaGetSymbolAddress((void**)&Ahi, g_Ahi);
    cudaGetSymbolAddress((void**)&Alo, g_Alo);
    cudaGetSymbolAddress((void**)&Wq,  g_Wq);
    cudaGetSymbolAddress((void**)&Wdh, g_Wd);
    cudaGetSymbolAddress((void**)&Att, g_Att);
    cudaGetSymbolAddress((void**)&Qhi, g_Qhi);
    cudaGetSymbolAddress((void**)&Qlo, g_Qlo);
    cudaGetSymbolAddress((void**)&Kt,  g_Kt);
    cudaGetSymbolAddress((void**)&Vp,  g_V);

    cudaFuncSetAttribute(gemm_fp16x2, cudaFuncAttributeMaxDynamicSharedMemorySize, GEMM2_SMEM);
    cudaFuncSetAttribute(gemm_fp16x1, cudaFuncAttributeMaxDynamicSharedMemorySize, GEMM1_SMEM);
    cudaFuncSetAttribute(rotary_split, cudaFuncAttributeMaxDynamicSharedMemorySize, ROT_SMEM);
    cudaFuncSetAttribute(flash_attn_mma, cudaFuncAttributeMaxDynamicSharedMemorySize, FA_SMEM);

    // 0) convert: hidden -> fp16 hi/lo; weights -> fp16 single
    split2_fp16<<<(B_ * S_ * HID_ / 4 + 255) / 256, 256>>>(hidden, Ahi, Alo, B_ * S_ * HID_ / 4);
    split1_fp16<<<(HID_ * 3 * HID_ / 4 + 255) / 256, 256>>>(Wqkv, Wq, HID_ * 3 * HID_ / 4);
    split1_fp16<<<(HID_ * HID_ / 4 + 255) / 256, 256>>>(Wd, Wdh, HID_ * HID_ / 4);

    // 1) QKV GEMM (fp16 A-split, 2 passes) + bias
    gemm_fp16x2<<<dim3((3 * HID_) / BN, (B_ * S_) / BM), 256, GEMM2_SMEM>>>(
        Ahi, Alo, Wq, bqkv, qkv, B_ * S_, 3 * HID_, HID_);

    // 2) rotary + fp16 split + K transpose
    rotary_split<<<dim3(S_ / 128, H_, B_), 256, ROT_SMEM>>>(
        qkv, pos, Qhi, Qlo, Kt, Vp);

    // 3) tensor-core causal flash attention (QK 2-pass, PV 1-pass)
    flash_attn_mma<<<dim3(S_ / 128, H_, B_), 256, FA_SMEM>>>(
        Qhi, Qlo, Kt, Vp, amask, Att);

    // 4) dense GEMM (fp16 single-pass) + bias
    gemm_fp16x1<<<dim3(HID_ / BN, (B_ * S_) / BM), 256, GEMM1_SMEM>>>(
        Att, Wdh, bd, out, B_ * S_, HID_, HID_);
}

// round 13
// speedup vs baseline: 1.4527x; 1.2747x over previous
#include <cuda_runtime.h>
#include <cuda_fp16.h>
#include <math.h>
#include <stdint.h>
#include <stddef.h>

#define B_   2
#define S_   2048
#define HID_ 2048
#define H_   16
#define HS_  128
#define RD_  32

// ---------------- scratch (device globals) ----------------
__device__ float g_qkv[(size_t)B_ * S_ * 3 * HID_];

__device__ __half g_A[(size_t)B_ * S_ * HID_];       // hidden, fp16 single
__device__ __half g_Wq[(size_t)HID_ * 3 * HID_];
__device__ __half g_Wd[(size_t)HID_ * HID_];
__device__ __half g_Att[(size_t)B_ * S_ * HID_];     // attn out, fp16 single

__device__ __half g_Qhi[(size_t)B_ * H_ * S_ * HS_];
__device__ __half g_Qlo[(size_t)B_ * H_ * S_ * HS_];
__device__ __half g_Kt[(size_t)B_ * H_ * HS_ * S_];
__device__ __half g_V[(size_t)B_ * H_ * S_ * HS_];

// ---------------- PTX helpers ----------------
__device__ __forceinline__ unsigned smem_u32(const void* p) {
    return (unsigned)__cvta_generic_to_shared(p);
}
__device__ __forceinline__ void cp16(unsigned s, const void* g) {
    asm volatile("cp.async.cg.shared.global [%0], [%1], 16;" :: "r"(s), "l"(g));
}
__device__ __forceinline__ void cp_commit() {
    asm volatile("cp.async.commit_group;");
}
__device__ __forceinline__ void cp_wait_1() {
    asm volatile("cp.async.wait_group 1;");
}
__device__ __forceinline__ void cp_wait_0() {
    asm volatile("cp.async.wait_group 0;");
}
__device__ __forceinline__ void ldm4(unsigned* r, unsigned a) {
    asm volatile("ldmatrix.sync.aligned.m8n8.x4.shared.b16 {%0,%1,%2,%3}, [%4];"
        : "=r"(r[0]), "=r"(r[1]), "=r"(r[2]), "=r"(r[3]) : "r"(a));
}
__device__ __forceinline__ void ldm4t(unsigned* r, unsigned a) {
    asm volatile("ldmatrix.sync.aligned.m8n8.x4.trans.shared.b16 {%0,%1,%2,%3}, [%4];"
        : "=r"(r[0]), "=r"(r[1]), "=r"(r[2]), "=r"(r[3]) : "r"(a));
}
__device__ __forceinline__ void mma16816(float* d, const unsigned* a, const unsigned* b) {
    asm volatile(
        "mma.sync.aligned.m16n8k16.row.col.f32.f16.f16.f32 "
        "{%0,%1,%2,%3},{%4,%5,%6,%7},{%8,%9},{%0,%1,%2,%3};"
        : "+f"(d[0]), "+f"(d[1]), "+f"(d[2]), "+f"(d[3])
        : "r"(a[0]), "r"(a[1]), "r"(a[2]), "r"(a[3]), "r"(b[0]), "r"(b[1]));
}

// ---------------- fp16 conversion ----------------
__global__ __launch_bounds__(256) void split1_fp16(
    const float* __restrict__ x, __half* __restrict__ out, int n4)
{
    int i = blockIdx.x * 256 + threadIdx.x;
    if (i >= n4) return;
    float4 v = ((const float4*)x)[i];
    ((__half2*)out)[i * 2 + 0] = __floats2half2_rn(v.x, v.y);
    ((__half2*)out)[i * 2 + 1] = __floats2half2_rn(v.z, v.w);
}

// ---------------- GEMM tile config ----------------
#define BM 128
#define BN 128
#define BK 32
#define A_STRIDE 40
#define B_STRIDE 136
#define A_BYTES (128 * A_STRIDE * 2)
#define B_BYTES (32 * B_STRIDE * 2)

// ================= fp16x1 GEMM (single pass): C = A @ B + bias =================
#define STAGE1_BYTES (A_BYTES + B_BYTES)           // 18944
#define GEMM1_SMEM (2 * STAGE1_BYTES)              // 37888

__device__ __forceinline__ void gemm1_load_stage(
    unsigned base, int t,
    const __half* __restrict__ As, const __half* __restrict__ Bs,
    int brow, int bcol, int k0, int K, int N)
{
    unsigned aS = base;
    unsigned bS = base + A_BYTES;
#pragma unroll
    for (int i = 0; i < 2; i++) {
        int c = t + i * 256;
        int ar = c >> 2;
        int ak = (c & 3) * 8;
        size_t ga = (size_t)(brow + ar) * K + k0 + ak;
        unsigned sa = (unsigned)(ar * A_STRIDE + ak) * 2u;
        cp16(aS + sa, As + ga);
        int br = c >> 4;
        int nn = (c & 15) * 8;
        size_t gb = (size_t)(k0 + br) * N + bcol + nn;
        unsigned sb = (unsigned)(br * B_STRIDE + nn) * 2u;
        cp16(bS + sb, Bs + gb);
    }
    cp_commit();
}

__device__ __forceinline__ void gemm1_compute_stage(
    unsigned base, int lane, int wm, int wn, float acc[4][4][4])
{
    unsigned aS = base;
    unsigned bS = base + A_BYTES;
#pragma unroll
    for (int kk = 0; kk < 32; kk += 16) {
        unsigned ah[4][4];
        const int arow = wm * 64 + (lane & 15);
        const int akc = kk + ((lane >> 4) << 3);
#pragma unroll
        for (int mt = 0; mt < 4; mt++) {
            unsigned ad = aS + (unsigned)((arow + mt * 16) * A_STRIDE + akc) * 2u;
            ldm4(ah[mt], ad);
        }
        unsigned bh[2][4];
        const int krow = kk + (lane & 15);
        const int nc0 = wn * 32 + ((lane >> 4) << 3);
#pragma unroll
        for (int np = 0; np < 2; np++) {
            unsigned bd = bS + (unsigned)(krow * B_STRIDE + nc0 + np * 16) * 2u;
            ldm4t(bh[np], bd);
        }
#pragma unroll
        for (int mt = 0; mt < 4; mt++)
#pragma unroll
            for (int np = 0; np < 2; np++)
#pragma unroll
                for (int hlf = 0; hlf < 2; hlf++)
                    mma16816(acc[mt][np * 2 + hlf], ah[mt], &bh[np][hlf * 2]);
    }
}

__global__ __launch_bounds__(256) void gemm_fp16x1(
    const __half* __restrict__ As, const __half* __restrict__ Bs,
    const float* __restrict__ bias, float* __restrict__ C,
    int M, int N, int K)
{
    extern __shared__ char dynsm[];
    const int t = threadIdx.x;
    const int lane = t & 31;
    const int warp = t >> 5;
    const int wm = warp >> 2;
    const int wn = warp & 3;
    const int brow = blockIdx.y * BM;
    const int bcol = blockIdx.x * BN;

    const unsigned smbase = smem_u32(dynsm);

    float acc[4][4][4];
#pragma unroll
    for (int i = 0; i < 4; i++)
#pragma unroll
        for (int j = 0; j < 4; j++)
#pragma unroll
            for (int k = 0; k < 4; k++) acc[i][j][k] = 0.f;

    const int niter = K / BK;
    gemm1_load_stage(smbase, t, As, Bs, brow, bcol, 0, K, N);
    for (int it = 0; it < niter; it++) {
        if (it + 1 < niter) {
            gemm1_load_stage(smbase + ((it + 1) & 1) * STAGE1_BYTES, t,
                             As, Bs, brow, bcol, (it + 1) * BK, K, N);
            cp_wait_1();
        } else {
            cp_wait_0();
        }
        __syncthreads();
        gemm1_compute_stage(smbase + (it & 1) * STAGE1_BYTES, lane, wm, wn, acc);
        __syncthreads();
    }

    const int g = lane >> 2;
    const int t2 = (lane & 3) * 2;
#pragma unroll
    for (int mt = 0; mt < 4; mt++) {
        int row = brow + wm * 64 + mt * 16 + g;
#pragma unroll
        for (int nt = 0; nt < 4; nt++) {
            int col = bcol + wn * 32 + nt * 8 + t2;
            float b0 = bias[col], b1 = bias[col + 1];
            float2 v0 = make_float2(acc[mt][nt][0] + b0, acc[mt][nt][1] + b1);
            float2 v1 = make_float2(acc[mt][nt][2] + b0, acc[mt][nt][3] + b1);
            *(float2*)(C + (size_t)row * N + col) = v0;
            *(float2*)(C + (size_t)(row + 8) * N + col) = v1;
        }
    }
}

// ---------------- rotary + split + scatter ----------------
#define ROT_SMEM (128 * 133 * 4)

__global__ __launch_bounds__(256) void rotary_split(
    const float* __restrict__ qkv, const int* __restrict__ pos,
    __half* __restrict__ Qhi, __half* __restrict__ Qlo,
    __half* __restrict__ Kt, __half* __restrict__ V)
{
    extern __shared__ char dynsm[];
    unsigned* ksm = (unsigned*)dynsm;

    const int t = threadIdx.x;
    const int s0 = blockIdx.x * 128;
    const int h = blockIdx.y, b = blockIdx.z;

#pragma unroll 4
    for (int i = 0; i < 64; i++) {
        int idx = t + i * 256;
        int d = idx & 127;
        int s = idx >> 7;
        const float* base = qkv + (size_t)(b * S_ + s0 + s) * (3 * HID_) + h * (3 * HS_);
        float q = base[d];
        float k = base[HS_ + d];
        float v = base[2 * HS_ + d];

        if (d < RD_) {
            float p = (float)pos[b * S_ + s0 + s];
            int fi = d & 15;
            float f = p * expf((float)(2 * fi) * (-1.0f / (float)RD_) * 9.210340371976184f);
            float c = cosf(f);
            float sn = sinf(f);
            int pd = (d < 16) ? d + 16 : d - 16;
            float sgn = (d < 16) ? -1.f : 1.f;
            float qp = base[pd];
            float kp = base[HS_ + pd];
            q = q * c + sgn * qp * sn;
            k = k * c + sgn * kp * sn;
        }

        size_t oi = ((size_t)(b * H_ + h) * S_ + s0 + s) * HS_ + d;
        __half qh = __float2half_rn(q);
        Qhi[oi] = qh;
        Qlo[oi] = __float2half_rn(q - __half2float(qh));
        V[oi] = __float2half_rn(v);

        __half kh = __float2half_rn(k);
        ksm[s * 133 + d] = (unsigned)__half_as_ushort(kh);
    }
    __syncthreads();

#pragma unroll 4
    for (int i = 0; i < 64; i++) {
        int idx = t + i * 256;
        int s = idx & 127;
        int d = idx >> 7;
        unsigned pk = ksm[s * 133 + d];
        size_t ko = ((size_t)(b * H_ + h) * HS_ + d) * S_ + s0 + s;
        Kt[ko] = __ushort_as_half((unsigned short)(pk & 0xffffu));
    }
}

// ---------------- tensor-core flash attention (causal; QK 2-pass, PV 1-pass) ----------------
#define FQ_STRIDE 136
#define FK_STRIDE 72
#define FV_STRIDE 136
#define FQ_BYTES (128 * FQ_STRIDE * 2)
#define FK_BYTES (128 * FK_STRIDE * 2)
#define FV_BYTES (64 * FV_STRIDE * 2)
#define FSTAGE   (FK_BYTES + FV_BYTES)
#define FA_SMEM  (2 * FQ_BYTES + 2 * FSTAGE)

__device__ __forceinline__ void fa_load_kv(
    unsigned base, int t,
    const __half* __restrict__ Kt, const __half* __restrict__ V,
    size_t bh, int k0)
{
    unsigned kS = base;
    unsigned vS = base + FK_BYTES;
#pragma unroll
    for (int i = 0; i < 4; i++) {
        int idx = t + i * 256;
        int kr = idx >> 3, kc = (idx & 7) * 8;
        size_t gk = bh + (size_t)kr * S_ + k0 + kc;
        unsigned sk = (unsigned)(kr * FK_STRIDE + kc) * 2u;
        cp16(kS + sk, Kt + gk);
        int vr = idx >> 4, vc = (idx & 15) * 8;
        size_t gv = bh + (size_t)(k0 + vr) * HS_ + vc;
        unsigned sv = (unsigned)(vr * FV_STRIDE + vc) * 2u;
        cp16(vS + sv, V + gv);
    }
}

__global__ __launch_bounds__(256) void flash_attn_mma(
    const __half* __restrict__ Qhi, const __half* __restrict__ Qlo,
    const __half* __restrict__ Kt,  const __half* __restrict__ V,
    const float* __restrict__ amask,
    __half* __restrict__ Out)
{
    extern __shared__ char dynsm[];
    const unsigned smb = smem_u32(dynsm);
    const unsigned sQh = smb;

    const int t = threadIdx.x, lane = t & 31, w = t >> 5;
    const int qt = gridDim.x - 1 - blockIdx.x;
    const int q0 = qt * 128;
    const int h = blockIdx.y, b = blockIdx.z;
    const size_t bh = (size_t)(b * H_ + h) * S_ * HS_;

#pragma unroll
    for (int i = 0; i < 8; i++) {
        int idx = t + i * 256;
        int r = idx >> 4, c = (idx & 15) * 8;
        size_t g = bh + (size_t)(q0 + r) * HS_ + c;
        unsigned so = (unsigned)(r * FQ_STRIDE + c) * 2u;
        cp16(sQh + so, Qhi + g);
        cp16(sQh + FQ_BYTES + so, Qlo + g);
    }
    fa_load_kv(smb + 2 * FQ_BYTES, t, Kt, V, bh, 0);
    cp_commit();

    float Oa[16][4];
#pragma unroll
    for (int i = 0; i < 16; i++)
#pragma unroll
        for (int j = 0; j < 4; j++) Oa[i][j] = 0.f;

    float m0 = -1e30f, m1 = -1e30f, l0 = 0.f, l1 = 0.f;
    const int nkt = 2 * (qt + 1);
    const float scale = 0.08838834764831845f;
    const int qrow0 = q0 + w * 16 + (lane >> 2);
    const int col_t = 2 * (lane & 3);

    for (int kt = 0; kt < nkt; kt++) {
        const int k0 = kt * 64;
        const unsigned stg = smb + 2 * FQ_BYTES + (kt & 1) * FSTAGE;
        if (kt + 1 < nkt) {
            fa_load_kv(smb + 2 * FQ_BYTES + ((kt + 1) & 1) * FSTAGE, t,
                       Kt, V, bh, (kt + 1) * 64);
            cp_commit();
            cp_wait_1();
        } else {
            cp_wait_0();
        }
        __syncthreads();

        float Sa[8][4];
#pragma unroll
        for (int i = 0; i < 8; i++)
#pragma unroll
            for (int j = 0; j < 4; j++) Sa[i][j] = 0.f;

#pragma unroll
        for (int kk = 0; kk < 8; kk++) {
            unsigned ah[4], al[4];
            unsigned qa = sQh + (unsigned)((w * 16 + (lane & 15)) * FQ_STRIDE
                                           + kk * 16 + ((lane >> 4) << 3)) * 2u;
            ldm4(ah, qa);
            ldm4(al, qa + FQ_BYTES);
#pragma unroll
            for (int nb = 0; nb < 4; nb++) {
                unsigned kh[4];
                unsigned ka = stg + (unsigned)((kk * 16 + (lane & 15)) * FK_STRIDE
                                               + nb * 16 + ((lane >> 4) << 3)) * 2u;
                ldm4t(kh, ka);
#pragma unroll
                for (int hf = 0; hf < 2; hf++) {
                    mma16816(Sa[nb * 2 + hf], ah, &kh[hf * 2]);
                    mma16816(Sa[nb * 2 + hf], al, &kh[hf * 2]);
                }
            }
        }

        const bool needmask = (k0 + 63 > q0 + w * 16);
        float mc0 = -1e30f, mc1 = -1e30f;
#pragma unroll
        for (int j = 0; j < 8; j++) {
            int cb = k0 + j * 8 + col_t;
            float a0 = amask[(size_t)b * S_ + cb];
            float a1 = amask[(size_t)b * S_ + cb + 1];
            Sa[j][0] = Sa[j][0] * scale + a0;
            Sa[j][1] = Sa[j][1] * scale + a1;
            Sa[j][2] = Sa[j][2] * scale + a0;
            Sa[j][3] = Sa[j][3] * scale + a1;
            if (needmask) {
                if (cb > qrow0)         Sa[j][0] = -1e30f;
                if (cb + 1 > qrow0)     Sa[j][1] = -1e30f;
                if (cb > qrow0 + 8)     Sa[j][2] = -1e30f;
                if (cb + 1 > qrow0 + 8) Sa[j][3] = -1e30f;
            }
            mc0 = fmaxf(mc0, fmaxf(Sa[j][0], Sa[j][1]));
            mc1 = fmaxf(mc1, fmaxf(Sa[j][2], Sa[j][3]));
        }
        mc0 = fmaxf(mc0, __shfl_xor_sync(0xffffffffu, mc0, 1));
        mc0 = fmaxf(mc0, __shfl_xor_sync(0xffffffffu, mc0, 2));
        mc1 = fmaxf(mc1, __shfl_xor_sync(0xffffffffu, mc1, 1));
        mc1 = fmaxf(mc1, __shfl_xor_sync(0xffffffffu, mc1, 2));

        float mn0 = fmaxf(m0, mc0), mn1 = fmaxf(m1, mc1);
        float sf0 = __expf(m0 - mn0), sf1 = __expf(m1 - mn1);
        m0 = mn0; m1 = mn1;

        float ps0 = 0.f, ps1 = 0.f;
        unsigned phi[4][4];
#pragma unroll
        for (int j = 0; j < 8; j++) {
            float p0 = __expf(Sa[j][0] - mn0);
            float p1 = __expf(Sa[j][1] - mn0);
            float p2 = __expf(Sa[j][2] - mn1);
            float p3 = __expf(Sa[j][3] - mn1);
            ps0 += p0 + p1;
            ps1 += p2 + p3;
            __half2 h01 = __floats2half2_rn(p0, p1);
            __half2 h23 = __floats2half2_rn(p2, p3);
            int kf = j >> 1, q = (j & 1) * 2;
            phi[kf][q + 0] = *reinterpret_cast<unsigned*>(&h01);
            phi[kf][q + 1] = *reinterpret_cast<unsigned*>(&h23);
        }
        ps0 += __shfl_xor_sync(0xffffffffu, ps0, 1);
        ps0 += __shfl_xor_sync(0xffffffffu, ps0, 2);
        ps1 += __shfl_xor_sync(0xffffffffu, ps1, 1);
        ps1 += __shfl_xor_sync(0xffffffffu, ps1, 2);
        l0 = l0 * sf0 + ps0;
        l1 = l1 * sf1 + ps1;

#pragma unroll
        for (int nb = 0; nb < 16; nb++) {
            Oa[nb][0] *= sf0; Oa[nb][1] *= sf0;
            Oa[nb][2] *= sf1; Oa[nb][3] *= sf1;
        }

        const unsigned vSb = stg + FK_BYTES;
#pragma unroll
        for (int kf = 0; kf < 4; kf++) {
#pragma unroll
            for (int nb = 0; nb < 8; nb++) {
                unsigned vh[4];
                unsigned va = vSb + (unsigned)((kf * 16 + (lane & 15)) * FV_STRIDE
                                               + nb * 16 + ((lane >> 4) << 3)) * 2u;
                ldm4t(vh, va);
#pragma unroll
                for (int hf = 0; hf < 2; hf++)
                    mma16816(Oa[nb * 2 + hf], phi[kf], &vh[hf * 2]);
            }
        }
        __syncthreads();
    }

    float rl0 = 1.0f / l0, rl1 = 1.0f / l1;
#pragma unroll
    for (int nb = 0; nb < 16; nb++) {
        int c = nb * 8 + col_t;
        __half2 h01 = __floats2half2_rn(Oa[nb][0] * rl0, Oa[nb][1] * rl0);
        __half2 h23 = __floats2half2_rn(Oa[nb][2] * rl1, Oa[nb][3] * rl1);
        size_t o0 = (size_t)(b * S_ + qrow0) * HID_ + h * HS_ + c;
        size_t o1 = o0 + (size_t)8 * HID_;
        *reinterpret_cast<__half2*>(Out + o0) = h01;
        *reinterpret_cast<__half2*>(Out + o1) = h23;
    }
}

// ---------------- launch ----------------
extern "C" void kernel_launch(void* const* d_in, const int* in_sizes, int n_in,
                              void* d_out, int out_size) {
    const float* hidden = (const float*)d_in[0];
    const float* amask  = (const float*)d_in[1];
    const int*   pos    = (const int*)d_in[2];
    const float* Wqkv   = (const float*)d_in[3];
    const float* bqkv   = (const float*)d_in[4];
    const float* Wd     = (const float*)d_in[5];
    const float* bd     = (const float*)d_in[6];
    float* out = (float*)d_out;

    float* qkv;
    __half *A, *Wq, *Wdh, *Att;
    __half *Qhi, *Qlo, *Kt, *Vp;
    cudaGetSymbolAddress((void**)&qkv, g_qkv);
    cudaGetSymbolAddress((void**)&A,   g_A);
    cudaGetSymbolAddress((void**)&Wq,  g_Wq);
    cudaGetSymbolAddress((void**)&Wdh, g_Wd);
    cudaGetSymbolAddress((void**)&Att, g_Att);
    cudaGetSymbolAddress((void**)&Qhi, g_Qhi);
    cudaGetSymbolAddress((void**)&Qlo, g_Qlo);
    cudaGetSymbolAddress((void**)&Kt,  g_Kt);
    cudaGetSymbolAddress((void**)&Vp,  g_V);

    cudaFuncSetAttribute(gemm_fp16x1, cudaFuncAttributeMaxDynamicSharedMemorySize, GEMM1_SMEM);
    cudaFuncSetAttribute(rotary_split, cudaFuncAttributeMaxDynamicSharedMemorySize, ROT_SMEM);
    cudaFuncSetAttribute(flash_attn_mma, cudaFuncAttributeMaxDynamicSharedMemorySize, FA_SMEM);

    // 0) convert inputs/weights to fp16
    split1_fp16<<<(B_ * S_ * HID_ / 4 + 255) / 256, 256>>>(hidden, A, B_ * S_ * HID_ / 4);
    split1_fp16<<<(HID_ * 3 * HID_ / 4 + 255) / 256, 256>>>(Wqkv, Wq, HID_ * 3 * HID_ / 4);
    split1_fp16<<<(HID_ * HID_ / 4 + 255) / 256, 256>>>(Wd, Wdh, HID_ * HID_ / 4);

    // 1) QKV GEMM (fp16 single-pass) + bias
    gemm_fp16x1<<<dim3((3 * HID_) / BN, (B_ * S_) / BM), 256, GEMM1_SMEM>>>(
        A, Wq, bqkv, qkv, B_ * S_, 3 * HID_, HID_);

    // 2) rotary + fp16 split + K transpose
    rotary_split<<<dim3(S_ / 128, H_, B_), 256, ROT_SMEM>>>(
        qkv, pos, Qhi, Qlo, Kt, Vp);

    // 3) tensor-core causal flash attention (QK 2-pass, PV 1-pass)
    flash_attn_mma<<<dim3(S_ / 128, H_, B_), 256, FA_SMEM>>>(
        Qhi, Qlo, Kt, Vp, amask, Att);

    // 4) dense GEMM (fp16 single-pass) + bias
    gemm_fp16x1<<<dim3(HID_ / BN, (B_ * S_) / BM), 256, GEMM1_SMEM>>>(
        Att, Wdh, bd, out, B_ * S_, HID_, HID_);
}

// round 15
// speedup vs baseline: 1.6569x; 1.1406x over previous
#include <cuda_runtime.h>
#include <cuda_fp16.h>
#include <math.h>
#include <stdint.h>
#include <stddef.h>

#define B_   2
#define S_   2048
#define HID_ 2048
#define H_   16
#define HS_  128
#define RD_  32

// ---------------- scratch (device globals) ----------------
__device__ float g_qkv[(size_t)B_ * S_ * 3 * HID_];

__device__ __half g_A[(size_t)B_ * S_ * HID_];       // hidden, fp16
__device__ __half g_Wq[(size_t)HID_ * 3 * HID_];
__device__ __half g_Wd[(size_t)HID_ * HID_];
__device__ __half g_Att[(size_t)B_ * S_ * HID_];     // attn out, fp16

__device__ __half g_Q[(size_t)B_ * H_ * S_ * HS_];   // [b,h,s,d]
__device__ __half g_Kt[(size_t)B_ * H_ * HS_ * S_];  // [b,h,d,s]
__device__ __half g_V[(size_t)B_ * H_ * S_ * HS_];

// ---------------- PTX helpers ----------------
__device__ __forceinline__ unsigned smem_u32(const void* p) {
    return (unsigned)__cvta_generic_to_shared(p);
}
__device__ __forceinline__ void cp16(unsigned s, const void* g) {
    asm volatile("cp.async.cg.shared.global [%0], [%1], 16;" :: "r"(s), "l"(g));
}
__device__ __forceinline__ void cp_commit() {
    asm volatile("cp.async.commit_group;");
}
__device__ __forceinline__ void cp_wait_1() {
    asm volatile("cp.async.wait_group 1;");
}
__device__ __forceinline__ void cp_wait_0() {
    asm volatile("cp.async.wait_group 0;");
}
__device__ __forceinline__ void ldm4(unsigned* r, unsigned a) {
    asm volatile("ldmatrix.sync.aligned.m8n8.x4.shared.b16 {%0,%1,%2,%3}, [%4];"
        : "=r"(r[0]), "=r"(r[1]), "=r"(r[2]), "=r"(r[3]) : "r"(a));
}
__device__ __forceinline__ void ldm4t(unsigned* r, unsigned a) {
    asm volatile("ldmatrix.sync.aligned.m8n8.x4.trans.shared.b16 {%0,%1,%2,%3}, [%4];"
        : "=r"(r[0]), "=r"(r[1]), "=r"(r[2]), "=r"(r[3]) : "r"(a));
}
__device__ __forceinline__ void mma16816(float* d, const unsigned* a, const unsigned* b) {
    asm volatile(
        "mma.sync.aligned.m16n8k16.row.col.f32.f16.f16.f32 "
        "{%0,%1,%2,%3},{%4,%5,%6,%7},{%8,%9},{%0,%1,%2,%3};"
        : "+f"(d[0]), "+f"(d[1]), "+f"(d[2]), "+f"(d[3])
        : "r"(a[0]), "r"(a[1]), "r"(a[2]), "r"(a[3]), "r"(b[0]), "r"(b[1]));
}

// ---------------- fp16 conversion ----------------
__global__ __launch_bounds__(256) void split1_fp16(
    const float* __restrict__ x, __half* __restrict__ out, int n4)
{
    int i = blockIdx.x * 256 + threadIdx.x;
    if (i >= n4) return;
    float4 v = ((const float4*)x)[i];
    ((__half2*)out)[i * 2 + 0] = __floats2half2_rn(v.x, v.y);
    ((__half2*)out)[i * 2 + 1] = __floats2half2_rn(v.z, v.w);
}

// ================= fp16 GEMM (single pass, BK=64): C = A @ B + bias =================
#define BM 128
#define BN 128
#define BK 64
#define A_STRIDE 72                                // 64 + 8 pad (halves)
#define B_STRIDE 136                               // 128 + 8 pad
#define A_BYTES (128 * A_STRIDE * 2)               // 18432
#define B_BYTES (64 * B_STRIDE * 2)                // 17408
#define STAGE1_BYTES (A_BYTES + B_BYTES)           // 35840
#define GEMM1_SMEM (2 * STAGE1_BYTES)              // 71680

__device__ __forceinline__ void gemm1_load_stage(
    unsigned base, int t,
    const __half* __restrict__ As, const __half* __restrict__ Bs,
    int brow, int bcol, int k0, int K, int N)
{
    unsigned aS = base;
    unsigned bS = base + A_BYTES;
#pragma unroll
    for (int i = 0; i < 4; i++) {                  // A: 1024 chunks (128 x 64)
        int c = t + i * 256;
        int ar = c >> 3;                           // 0..127
        int ak = (c & 7) * 8;                      // 0..56
        size_t ga = (size_t)(brow + ar) * K + k0 + ak;
        unsigned sa = (unsigned)(ar * A_STRIDE + ak) * 2u;
        cp16(aS + sa, As + ga);
    }
#pragma unroll
    for (int i = 0; i < 4; i++) {                  // B: 1024 chunks (64 x 128)
        int c = t + i * 256;
        int br = c >> 4;                           // 0..63
        int nn = (c & 15) * 8;                     // 0..120
        size_t gb = (size_t)(k0 + br) * N + bcol + nn;
        unsigned sb = (unsigned)(br * B_STRIDE + nn) * 2u;
        cp16(bS + sb, Bs + gb);
    }
    cp_commit();
}

__device__ __forceinline__ void gemm1_compute_stage(
    unsigned base, int lane, int wm, int wn, float acc[4][4][4])
{
    unsigned aS = base;
    unsigned bS = base + A_BYTES;
#pragma unroll
    for (int kk = 0; kk < 64; kk += 16) {
        unsigned ah[4][4];
        const int arow = wm * 64 + (lane & 15);
        const int akc = kk + ((lane >> 4) << 3);
#pragma unroll
        for (int mt = 0; mt < 4; mt++) {
            unsigned ad = aS + (unsigned)((arow + mt * 16) * A_STRIDE + akc) * 2u;
            ldm4(ah[mt], ad);
        }
        unsigned bh[2][4];
        const int krow = kk + (lane & 15);
        const int nc0 = wn * 32 + ((lane >> 4) << 3);
#pragma unroll
        for (int np = 0; np < 2; np++) {
            unsigned bd = bS + (unsigned)(krow * B_STRIDE + nc0 + np * 16) * 2u;
            ldm4t(bh[np], bd);
        }
#pragma unroll
        for (int mt = 0; mt < 4; mt++)
#pragma unroll
            for (int np = 0; np < 2; np++)
#pragma unroll
                for (int hlf = 0; hlf < 2; hlf++)
                    mma16816(acc[mt][np * 2 + hlf], ah[mt], &bh[np][hlf * 2]);
    }
}

__global__ __launch_bounds__(256) void gemm_fp16x1(
    const __half* __restrict__ As, const __half* __restrict__ Bs,
    const float* __restrict__ bias, float* __restrict__ C,
    int M, int N, int K)
{
    extern __shared__ char dynsm[];
    const int t = threadIdx.x;
    const int lane = t & 31;
    const int warp = t >> 5;
    const int wm = warp >> 2;
    const int wn = warp & 3;
    const int brow = blockIdx.y * BM;
    const int bcol = blockIdx.x * BN;

    const unsigned smbase = smem_u32(dynsm);

    float acc[4][4][4];
#pragma unroll
    for (int i = 0; i < 4; i++)
#pragma unroll
        for (int j = 0; j < 4; j++)
#pragma unroll
            for (int k = 0; k < 4; k++) acc[i][j][k] = 0.f;

    const int niter = K / BK;
    gemm1_load_stage(smbase, t, As, Bs, brow, bcol, 0, K, N);
    for (int it = 0; it < niter; it++) {
        if (it + 1 < niter) {
            gemm1_load_stage(smbase + ((it + 1) & 1) * STAGE1_BYTES, t,
                             As, Bs, brow, bcol, (it + 1) * BK, K, N);
            cp_wait_1();
        } else {
            cp_wait_0();
        }
        __syncthreads();
        gemm1_compute_stage(smbase + (it & 1) * STAGE1_BYTES, lane, wm, wn, acc);
        __syncthreads();
    }

    const int g = lane >> 2;
    const int t2 = (lane & 3) * 2;
#pragma unroll
    for (int mt = 0; mt < 4; mt++) {
        int row = brow + wm * 64 + mt * 16 + g;
#pragma unroll
        for (int nt = 0; nt < 4; nt++) {
            int col = bcol + wn * 32 + nt * 8 + t2;
            float b0 = bias[col], b1 = bias[col + 1];
            float2 v0 = make_float2(acc[mt][nt][0] + b0, acc[mt][nt][1] + b1);
            float2 v1 = make_float2(acc[mt][nt][2] + b0, acc[mt][nt][3] + b1);
            *(float2*)(C + (size_t)row * N + col) = v0;
            *(float2*)(C + (size_t)(row + 8) * N + col) = v1;
        }
    }
}

// ---------------- rotary + fp16 + scatter (Q,V natural; K transposed) ----------------
#define ROT_SMEM (128 * 133 * 4)

__global__ __launch_bounds__(256) void rotary_split(
    const float* __restrict__ qkv, const int* __restrict__ pos,
    __half* __restrict__ Q, __half* __restrict__ Kt, __half* __restrict__ V)
{
    extern __shared__ char dynsm[];
    unsigned* ksm = (unsigned*)dynsm;

    const int t = threadIdx.x;
    const int s0 = blockIdx.x * 128;
    const int h = blockIdx.y, b = blockIdx.z;

#pragma unroll 4
    for (int i = 0; i < 64; i++) {
        int idx = t + i * 256;
        int d = idx & 127;
        int s = idx >> 7;
        const float* base = qkv + (size_t)(b * S_ + s0 + s) * (3 * HID_) + h * (3 * HS_);
        float q = base[d];
        float k = base[HS_ + d];
        float v = base[2 * HS_ + d];

        if (d < RD_) {
            float p = (float)pos[b * S_ + s0 + s];
            int fi = d & 15;
            float f = p * expf((float)(2 * fi) * (-1.0f / (float)RD_) * 9.210340371976184f);
            float c = cosf(f);
            float sn = sinf(f);
            int pd = (d < 16) ? d + 16 : d - 16;
            float sgn = (d < 16) ? -1.f : 1.f;
            float qp = base[pd];
            float kp = base[HS_ + pd];
            q = q * c + sgn * qp * sn;
            k = k * c + sgn * kp * sn;
        }

        size_t oi = ((size_t)(b * H_ + h) * S_ + s0 + s) * HS_ + d;
        Q[oi] = __float2half_rn(q);
        V[oi] = __float2half_rn(v);

        __half kh = __float2half_rn(k);
        ksm[s * 133 + d] = (unsigned)__half_as_ushort(kh);
    }
    __syncthreads();

#pragma unroll 4
    for (int i = 0; i < 64; i++) {
        int idx = t + i * 256;
        int s = idx & 127;
        int d = idx >> 7;
        unsigned pk = ksm[s * 133 + d];
        size_t ko = ((size_t)(b * H_ + h) * HS_ + d) * S_ + s0 + s;
        Kt[ko] = __ushort_as_half((unsigned short)(pk & 0xffffu));
    }
}

// ---------------- tensor-core flash attention (causal; fp16 single-pass) ----------------
#define FQ_STRIDE 136
#define FK_STRIDE 72
#define FV_STRIDE 136
#define FQ_BYTES (128 * FQ_STRIDE * 2)
#define FK_BYTES (128 * FK_STRIDE * 2)
#define FV_BYTES (64 * FV_STRIDE * 2)
#define FSTAGE   (FK_BYTES + FV_BYTES)
#define FA_SMEM  (FQ_BYTES + 2 * FSTAGE)

__device__ __forceinline__ void fa_load_kv(
    unsigned base, int t,
    const __half* __restrict__ Kt, const __half* __restrict__ V,
    size_t bh, int k0)
{
    unsigned kS = base;
    unsigned vS = base + FK_BYTES;
#pragma unroll
    for (int i = 0; i < 4; i++) {
        int idx = t + i * 256;
        int kr = idx >> 3, kc = (idx & 7) * 8;
        size_t gk = bh + (size_t)kr * S_ + k0 + kc;
        unsigned sk = (unsigned)(kr * FK_STRIDE + kc) * 2u;
        cp16(kS + sk, Kt + gk);
        int vr = idx >> 4, vc = (idx & 15) * 8;
        size_t gv = bh + (size_t)(k0 + vr) * HS_ + vc;
        unsigned sv = (unsigned)(vr * FV_STRIDE + vc) * 2u;
        cp16(vS + sv, V + gv);
    }
}

__global__ __launch_bounds__(256) void flash_attn_mma(
    const __half* __restrict__ Q, const __half* __restrict__ Kt,
    const __half* __restrict__ V, const float* __restrict__ amask,
    __half* __restrict__ Out)
{
    extern __shared__ char dynsm[];
    const unsigned smb = smem_u32(dynsm);
    const unsigned sQ = smb;
    const unsigned sKV = smb + FQ_BYTES;

    const int t = threadIdx.x, lane = t & 31, w = t >> 5;
    const int qt = gridDim.x - 1 - blockIdx.x;
    const int q0 = qt * 128;
    const int h = blockIdx.y, b = blockIdx.z;
    const size_t bh = (size_t)(b * H_ + h) * S_ * HS_;

#pragma unroll
    for (int i = 0; i < 8; i++) {
        int idx = t + i * 256;
        int r = idx >> 4, c = (idx & 15) * 8;
        size_t g = bh + (size_t)(q0 + r) * HS_ + c;
        cp16(sQ + (unsigned)(r * FQ_STRIDE + c) * 2u, Q + g);
    }
    fa_load_kv(sKV, t, Kt, V, bh, 0);
    cp_commit();

    float Oa[16][4];
#pragma unroll
    for (int i = 0; i < 16; i++)
#pragma unroll
        for (int j = 0; j < 4; j++) Oa[i][j] = 0.f;

    float m0 = -1e30f, m1 = -1e30f, l0 = 0.f, l1 = 0.f;
    const int nkt = 2 * (qt + 1);
    const float scale = 0.08838834764831845f;
    const int qrow0 = q0 + w * 16 + (lane >> 2);
    const int col_t = 2 * (lane & 3);

    for (int kt = 0; kt < nkt; kt++) {
        const int k0 = kt * 64;
        const unsigned stg = sKV + (kt & 1) * FSTAGE;
        if (kt + 1 < nkt) {
            fa_load_kv(sKV + ((kt + 1) & 1) * FSTAGE, t, Kt, V, bh, (kt + 1) * 64);
            cp_commit();
            cp_wait_1();
        } else {
            cp_wait_0();
        }
        __syncthreads();

        float Sa[8][4];
#pragma unroll
        for (int i = 0; i < 8; i++)
#pragma unroll
            for (int j = 0; j < 4; j++) Sa[i][j] = 0.f;

#pragma unroll
        for (int kk = 0; kk < 8; kk++) {
            unsigned ah[4];
            unsigned qa = sQ + (unsigned)((w * 16 + (lane & 15)) * FQ_STRIDE
                                          + kk * 16 + ((lane >> 4) << 3)) * 2u;
            ldm4(ah, qa);
#pragma unroll
            for (int nb = 0; nb < 4; nb++) {
                unsigned kh[4];
                unsigned ka = stg + (unsigned)((kk * 16 + (lane & 15)) * FK_STRIDE
                                               + nb * 16 + ((lane >> 4) << 3)) * 2u;
                ldm4t(kh, ka);
#pragma unroll
                for (int hf = 0; hf < 2; hf++)
                    mma16816(Sa[nb * 2 + hf], ah, &kh[hf * 2]);
            }
        }

        const bool needmask = (k0 + 63 > q0 + w * 16);
        float mc0 = -1e30f, mc1 = -1e30f;
#pragma unroll
        for (int j = 0; j < 8; j++) {
            int cb = k0 + j * 8 + col_t;
            float a0 = amask[(size_t)b * S_ + cb];
            float a1 = amask[(size_t)b * S_ + cb + 1];
            Sa[j][0] = Sa[j][0] * scale + a0;
            Sa[j][1] = Sa[j][1] * scale + a1;
            Sa[j][2] = Sa[j][2] * scale + a0;
            Sa[j][3] = Sa[j][3] * scale + a1;
            if (needmask) {
                if (cb > qrow0)         Sa[j][0] = -1e30f;
                if (cb + 1 > qrow0)     Sa[j][1] = -1e30f;
                if (cb > qrow0 + 8)     Sa[j][2] = -1e30f;
                if (cb + 1 > qrow0 + 8) Sa[j][3] = -1e30f;
            }
            mc0 = fmaxf(mc0, fmaxf(Sa[j][0], Sa[j][1]));
            mc1 = fmaxf(mc1, fmaxf(Sa[j][2], Sa[j][3]));
        }
        mc0 = fmaxf(mc0, __shfl_xor_sync(0xffffffffu, mc0, 1));
        mc0 = fmaxf(mc0, __shfl_xor_sync(0xffffffffu, mc0, 2));
        mc1 = fmaxf(mc1, __shfl_xor_sync(0xffffffffu, mc1, 1));
        mc1 = fmaxf(mc1, __shfl_xor_sync(0xffffffffu, mc1, 2));

        float mn0 = fmaxf(m0, mc0), mn1 = fmaxf(m1, mc1);
        float sf0 = __expf(m0 - mn0), sf1 = __expf(m1 - mn1);
        m0 = mn0; m1 = mn1;

        float ps0 = 0.f, ps1 = 0.f;
        unsigned phi[4][4];
#pragma unroll
        for (int j = 0; j < 8; j++) {
            float p0 = __expf(Sa[j][0] - mn0);
            float p1 = __expf(Sa[j][1] - mn0);
            float p2 = __expf(Sa[j][2] - mn1);
            float p3 = __expf(Sa[j][3] - mn1);
            ps0 += p0 + p1;
            ps1 += p2 + p3;
            __half2 h01 = __floats2half2_rn(p0, p1);
            __half2 h23 = __floats2half2_rn(p2, p3);
            int kf = j >> 1, q = (j & 1) * 2;
            phi[kf][q + 0] = *reinterpret_cast<unsigned*>(&h01);
            phi[kf][q + 1] = *reinterpret_cast<unsigned*>(&h23);
        }
        ps0 += __shfl_xor_sync(0xffffffffu, ps0, 1);
        ps0 += __shfl_xor_sync(0xffffffffu, ps0, 2);
        ps1 += __shfl_xor_sync(0xffffffffu, ps1, 1);
        ps1 += __shfl_xor_sync(0xffffffffu, ps1, 2);
        l0 = l0 * sf0 + ps0;
        l1 = l1 * sf1 + ps1;

#pragma unroll
        for (int nb = 0; nb < 16; nb++) {
            Oa[nb][0] *= sf0; Oa[nb][1] *= sf0;
            Oa[nb][2] *= sf1; Oa[nb][3] *= sf1;
        }

        const unsigned vSb = stg + FK_BYTES;
#pragma unroll
        for (int kf = 0; kf < 4; kf++) {
#pragma unroll
            for (int nb = 0; nb < 8; nb++) {
                unsigned vh[4];
                unsigned va = vSb + (unsigned)((kf * 16 + (lane & 15)) * FV_STRIDE
                                               + nb * 16 + ((lane >> 4) << 3)) * 2u;
                ldm4t(vh, va);
#pragma unroll
                for (int hf = 0; hf < 2; hf++)
                    mma16816(Oa[nb * 2 + hf], phi[kf], &vh[hf * 2]);
            }
        }
        __syncthreads();
    }

    float rl0 = 1.0f / l0, rl1 = 1.0f / l1;
#pragma unroll
    for (int nb = 0; nb < 16; nb++) {
        int c = nb * 8 + col_t;
        __half2 h01 = __floats2half2_rn(Oa[nb][0] * rl0, Oa[nb][1] * rl0);
        __half2 h23 = __floats2half2_rn(Oa[nb][2] * rl1, Oa[nb][3] * rl1);
        size_t o0 = (size_t)(b * S_ + qrow0) * HID_ + h * HS_ + c;
        size_t o1 = o0 + (size_t)8 * HID_;
        *reinterpret_cast<__half2*>(Out + o0) = h01;
        *reinterpret_cast<__half2*>(Out + o1) = h23;
    }
}

// ---------------- launch ----------------
extern "C" void kernel_launch(void* const* d_in, const int* in_sizes, int n_in,
                              void* d_out, int out_size) {
    const float* hidden = (const float*)d_in[0];
    const float* amask  = (const float*)d_in[1];
    const int*   pos    = (const int*)d_in[2];
    const float* Wqkv   = (const float*)d_in[3];
    const float* bqkv   = (const float*)d_in[4];
    const float* Wd     = (const float*)d_in[5];
    const float* bd     = (const float*)d_in[6];
    float* out = (float*)d_out;

    float* qkv;
    __half *A, *Wq, *Wdh, *Att, *Qp, *Kt, *Vp;
    cudaGetSymbolAddress((void**)&qkv, g_qkv);
    cudaGetSymbolAddress((void**)&A,   g_A);
    cudaGetSymbolAddress((void**)&Wq,  g_Wq);
    cudaGetSymbolAddress((void**)&Wdh, g_Wd);
    cudaGetSymbolAddress((void**)&Att, g_Att);
    cudaGetSymbolAddress((void**)&Qp,  g_Q);
    cudaGetSymbolAddress((void**)&Kt,  g_Kt);
    cudaGetSymbolAddress((void**)&Vp,  g_V);

    cudaFuncSetAttribute(gemm_fp16x1, cudaFuncAttributeMaxDynamicSharedMemorySize, GEMM1_SMEM);
    cudaFuncSetAttribute(rotary_split, cudaFuncAttributeMaxDynamicSharedMemorySize, ROT_SMEM);
    cudaFuncSetAttribute(flash_attn_mma, cudaFuncAttributeMaxDynamicSharedMemorySize, FA_SMEM);

    // 0) convert inputs/weights to fp16
    split1_fp16<<<(B_ * S_ * HID_ / 4 + 255) / 256, 256>>>(hidden, A, B_ * S_ * HID_ / 4);
    split1_fp16<<<(HID_ * 3 * HID_ / 4 + 255) / 256, 256>>>(Wqkv, Wq, HID_ * 3 * HID_ / 4);
    split1_fp16<<<(HID_ * HID_ / 4 + 255) / 256, 256>>>(Wd, Wdh, HID_ * HID_ / 4);

    // 1) QKV GEMM + bias
    gemm_fp16x1<<<dim3((3 * HID_) / BN, (B_ * S_) / BM), 256, GEMM1_SMEM>>>(
        A, Wq, bqkv, qkv, B_ * S_, 3 * HID_, HID_);

    // 2) rotary + fp16 + K transpose
    rotary_split<<<dim3(S_ / 128, H_, B_), 256, ROT_SMEM>>>(qkv, pos, Qp, Kt, Vp);

    // 3) tensor-core causal flash attention
    flash_attn_mma<<<dim3(S_ / 128, H_, B_), 256, FA_SMEM>>>(Qp, Kt, Vp, amask, Att);

    // 4) dense GEMM + bias
    gemm_fp16x1<<<dim3(HID_ / BN, (B_ * S_) / BM), 256, GEMM1_SMEM>>>(
        Att, Wdh, bd, out, B_ * S_, HID_, HID_);
}